// round 1
// baseline (speedup 1.0000x reference)
#include <cuda_runtime.h>
#include <cstdint>
#include <cstddef>

// ---------------------------------------------------------------------------
// CausalSelfAttention: out = proj( causal_attn( x @ Wqkv^T ) )
//   x      : [4, 2048, 1024] fp32
//   w_attn : [3072, 1024]    fp32   (applied as x @ W^T)
//   w_proj : [1024, 1024]    fp32
//   out    : [4, 2048, 1024] fp32
// Pipeline: GEMM1 (qkv) -> fused flash attention -> GEMM2 (proj)
// ---------------------------------------------------------------------------

#define BATCH   4
#define S_LEN   2048
#define D_MODEL 1024
#define D3      3072
#define N_HEADS 16
#define DH      64
#define M_ROWS  (BATCH * S_LEN)   // 8192

// Scratch (no cudaMalloc allowed)
__device__ float g_qkv[(size_t)M_ROWS * D3];      // ~100.7 MB
__device__ float g_y[(size_t)M_ROWS * D_MODEL];   // ~33.6 MB

// ---------------------------------------------------------------------------
// GEMM (NT): C[M,N] = A[M,K] @ B[N,K]^T, all row-major, K-contiguous.
// Tiles: BM=128, BN=64, BK=16. 256 threads, per-thread micro-tile 4x8.
// ---------------------------------------------------------------------------
#define GBM 128
#define GBN 64
#define GBK 16

__global__ __launch_bounds__(256, 2)
void gemm_nt(const float* __restrict__ A, const float* __restrict__ B,
             float* __restrict__ C, int M, int N, int K) {
    __shared__ float As[GBM][GBK + 1];   // [row][k], pad for bank spread
    __shared__ float Bst[GBK][GBN];      // [k][col] (transposed for float4 reads)

    const int tid = threadIdx.x;
    const int tx  = tid & 7;     // 0..7  -> 8 cols
    const int ty  = tid >> 3;    // 0..31 -> 4 rows each
    const int row0 = blockIdx.y * GBM;
    const int col0 = blockIdx.x * GBN;

    const float* Ab = A + (size_t)row0 * K;
    const float* Bb = B + (size_t)col0 * K;

    float acc[4][8];
#pragma unroll
    for (int i = 0; i < 4; i++)
#pragma unroll
        for (int j = 0; j < 8; j++) acc[i][j] = 0.f;

    for (int k0 = 0; k0 < K; k0 += GBK) {
        // Load A tile: 128x16 floats = 512 float4, 2 per thread
#pragma unroll
        for (int r = 0; r < 2; r++) {
            int p = tid + 256 * r;          // float4 index
            int arow = p >> 2;
            int akq  = p & 3;
            float4 v = *(const float4*)(Ab + (size_t)arow * K + k0 + akq * 4);
            float* d = &As[arow][akq * 4];
            d[0] = v.x; d[1] = v.y; d[2] = v.z; d[3] = v.w;
        }
        // Load B tile transposed: 64x16 floats = 256 float4, 1 per thread
        {
            int brow = tid >> 2;
            int bkq  = tid & 3;
            float4 v = *(const float4*)(Bb + (size_t)brow * K + k0 + bkq * 4);
            Bst[bkq * 4 + 0][brow] = v.x;
            Bst[bkq * 4 + 1][brow] = v.y;
            Bst[bkq * 4 + 2][brow] = v.z;
            Bst[bkq * 4 + 3][brow] = v.w;
        }
        __syncthreads();

#pragma unroll
        for (int k = 0; k < GBK; k++) {
            float a[4];
#pragma unroll
            for (int i = 0; i < 4; i++) a[i] = As[ty * 4 + i][k];
            float4 b0 = *(const float4*)&Bst[k][tx * 8];
            float4 b1 = *(const float4*)&Bst[k][tx * 8 + 4];
            float bb[8] = {b0.x, b0.y, b0.z, b0.w, b1.x, b1.y, b1.z, b1.w};
#pragma unroll
            for (int i = 0; i < 4; i++)
#pragma unroll
                for (int j = 0; j < 8; j++)
                    acc[i][j] = fmaf(a[i], bb[j], acc[i][j]);
        }
        __syncthreads();
    }

#pragma unroll
    for (int i = 0; i < 4; i++) {
        float* Crow = C + (size_t)(row0 + ty * 4 + i) * N + col0 + tx * 8;
        float4 v0 = {acc[i][0], acc[i][1], acc[i][2], acc[i][3]};
        float4 v1 = {acc[i][4], acc[i][5], acc[i][6], acc[i][7]};
        *(float4*)(Crow)     = v0;
        *(float4*)(Crow + 4) = v1;
    }
}

// ---------------------------------------------------------------------------
// Fused causal flash attention (fp32). One block per (q-tile, head, batch).
// BQ=128 query rows, BKV=64 kv rows per inner tile. 256 threads: ty in
// [0,32) owns 4 rows, tx in [0,8) owns 8 cols. Online softmax; row stats
// replicated across the 8 tx lanes via shfl butterflies.
// ---------------------------------------------------------------------------
#define ATT_BQ 128
#define ATT_BK 64

__global__ __launch_bounds__(256, 2)
void attn_kernel(const float* __restrict__ qkv, float* __restrict__ y) {
    extern __shared__ float sm[];
    float* Qs  = sm;                 // 128 x 65 (padded)
    float* Ps  = Qs + 128 * 65;      // 128 x 65 (padded)
    float* Kst = Ps + 128 * 65;      // 64 x 64  (dim-major: Kst[d][n])
    float* Vs  = Kst + 64 * 64;      // 64 x 64  ([n][d])

    const int tid = threadIdx.x;
    const int tx  = tid & 7;
    const int ty  = tid >> 3;
    const int qi  = blockIdx.x;      // 0..15
    const int h   = blockIdx.y;
    const int b   = blockIdx.z;
    const int q0  = qi * ATT_BQ;

    const float* base = qkv + (size_t)b * S_LEN * D3;

    // Load Q tile (128 x 64), pre-scaled by 1/sqrt(Dh) = 0.125
#pragma unroll
    for (int r = 0; r < 8; r++) {
        int p   = tid + 256 * r;     // float4 idx, 0..2047
        int row = p >> 4;
        int kq  = p & 15;
        float4 v = *(const float4*)(base + (size_t)(q0 + row) * D3 + h * DH + kq * 4);
        float* d = Qs + row * 65 + kq * 4;
        d[0] = v.x * 0.125f; d[1] = v.y * 0.125f; d[2] = v.z * 0.125f; d[3] = v.w * 0.125f;
    }

    float m[4], l[4], o[4][8];
#pragma unroll
    for (int i = 0; i < 4; i++) {
        m[i] = -1e30f; l[i] = 0.f;
#pragma unroll
        for (int j = 0; j < 8; j++) o[i][j] = 0.f;
    }

    const int njb = 2 * qi + 2;      // kv tiles covering cols 0..q0+127
    for (int jb = 0; jb < njb; jb++) {
        const int k0 = jb * ATT_BK;
        __syncthreads();             // prior iter done reading Vs/Ps

        // Load K (transposed to dim-major) and V tiles
#pragma unroll
        for (int r = 0; r < 4; r++) {
            int p   = tid + 256 * r; // float4 idx over 64x16
            int row = p >> 4;
            int kq  = p & 15;
            const float* gk = base + (size_t)(k0 + row) * D3 + D_MODEL + h * DH + kq * 4;
            float4 kv4 = *(const float4*)gk;
            Kst[(kq * 4 + 0) * 64 + row] = kv4.x;
            Kst[(kq * 4 + 1) * 64 + row] = kv4.y;
            Kst[(kq * 4 + 2) * 64 + row] = kv4.z;
            Kst[(kq * 4 + 3) * 64 + row] = kv4.w;
            const float* gv = base + (size_t)(k0 + row) * D3 + 2 * D_MODEL + h * DH + kq * 4;
            *(float4*)(Vs + row * 64 + kq * 4) = *(const float4*)gv;
        }
        __syncthreads();

        // S = Q @ K^T (per-thread 4x8)
        float s[4][8];
#pragma unroll
        for (int i = 0; i < 4; i++)
#pragma unroll
            for (int j = 0; j < 8; j++) s[i][j] = 0.f;

#pragma unroll 8
        for (int k = 0; k < 64; k++) {
            float a[4];
#pragma unroll
            for (int i = 0; i < 4; i++) a[i] = Qs[(ty * 4 + i) * 65 + k];
            float4 b0 = *(const float4*)(Kst + k * 64 + tx * 8);
            float4 b1 = *(const float4*)(Kst + k * 64 + tx * 8 + 4);
            float bb[8] = {b0.x, b0.y, b0.z, b0.w, b1.x, b1.y, b1.z, b1.w};
#pragma unroll
            for (int i = 0; i < 4; i++)
#pragma unroll
                for (int j = 0; j < 8; j++)
                    s[i][j] = fmaf(a[i], bb[j], s[i][j]);
        }

        // Causal mask (only last two kv tiles can intersect the diagonal)
        if (k0 + ATT_BK - 1 > q0) {
#pragma unroll
            for (int i = 0; i < 4; i++) {
                int rg = q0 + ty * 4 + i;
#pragma unroll
                for (int j = 0; j < 8; j++) {
                    int cg = k0 + tx * 8 + j;
                    if (cg > rg) s[i][j] = -1e30f;
                }
            }
        }

        // Online softmax update
#pragma unroll
        for (int i = 0; i < 4; i++) {
            float rmax = s[i][0];
#pragma unroll
            for (int j = 1; j < 8; j++) rmax = fmaxf(rmax, s[i][j]);
            rmax = fmaxf(rmax, __shfl_xor_sync(0xffffffffu, rmax, 1));
            rmax = fmaxf(rmax, __shfl_xor_sync(0xffffffffu, rmax, 2));
            rmax = fmaxf(rmax, __shfl_xor_sync(0xffffffffu, rmax, 4));
            float mnew  = fmaxf(m[i], rmax);
            float alpha = __expf(m[i] - mnew);
            m[i] = mnew;
            float rsum = 0.f;
#pragma unroll
            for (int j = 0; j < 8; j++) {
                float p = __expf(s[i][j] - mnew);
                s[i][j] = p;
                rsum += p;
            }
            rsum += __shfl_xor_sync(0xffffffffu, rsum, 1);
            rsum += __shfl_xor_sync(0xffffffffu, rsum, 2);
            rsum += __shfl_xor_sync(0xffffffffu, rsum, 4);
            l[i] = l[i] * alpha + rsum;
#pragma unroll
            for (int j = 0; j < 8; j++) o[i][j] *= alpha;
        }

        // Stage P into shared
#pragma unroll
        for (int i = 0; i < 4; i++) {
            float* pr = Ps + (ty * 4 + i) * 65 + tx * 8;
#pragma unroll
            for (int j = 0; j < 8; j++) pr[j] = s[i][j];
        }
        __syncthreads();

        // O += P @ V
#pragma unroll 8
        for (int k = 0; k < 64; k++) {
            float a[4];
#pragma unroll
            for (int i = 0; i < 4; i++) a[i] = Ps[(ty * 4 + i) * 65 + k];
            float4 b0 = *(const float4*)(Vs + k * 64 + tx * 8);
            float4 b1 = *(const float4*)(Vs + k * 64 + tx * 8 + 4);
            float bb[8] = {b0.x, b0.y, b0.z, b0.w, b1.x, b1.y, b1.z, b1.w};
#pragma unroll
            for (int i = 0; i < 4; i++)
#pragma unroll
                for (int j = 0; j < 8; j++)
                    o[i][j] = fmaf(a[i], bb[j], o[i][j]);
        }
    }

    // Epilogue: normalize and write y[b, q0+row, h*64 + col]
#pragma unroll
    for (int i = 0; i < 4; i++) {
        float inv = 1.0f / l[i];
        int rg = q0 + ty * 4 + i;
        float* yr = y + ((size_t)b * S_LEN + rg) * D_MODEL + h * DH + tx * 8;
        float4 v0 = {o[i][0] * inv, o[i][1] * inv, o[i][2] * inv, o[i][3] * inv};
        float4 v1 = {o[i][4] * inv, o[i][5] * inv, o[i][6] * inv, o[i][7] * inv};
        *(float4*)(yr)     = v0;
        *(float4*)(yr + 4) = v1;
    }
}

// ---------------------------------------------------------------------------
// Launch
// ---------------------------------------------------------------------------
extern "C" void kernel_launch(void* const* d_in, const int* in_sizes, int n_in,
                              void* d_out, int out_size) {
    const float* x      = (const float*)d_in[0];
    const float* w_attn = (const float*)d_in[1];
    const float* w_proj = (const float*)d_in[2];
    float* out = (float*)d_out;

    float *qkv = nullptr, *yb = nullptr;
    cudaGetSymbolAddress((void**)&qkv, g_qkv);
    cudaGetSymbolAddress((void**)&yb, g_y);

    const int attn_smem = (128 * 65 * 2 + 64 * 64 * 2) * (int)sizeof(float); // 99328 B
    cudaFuncSetAttribute(attn_kernel, cudaFuncAttributeMaxDynamicSharedMemorySize, attn_smem);

    // GEMM1: qkv = x @ w_attn^T   [8192 x 3072, K=1024]
    dim3 g1(D3 / GBN, M_ROWS / GBM);
    gemm_nt<<<g1, 256>>>(x, w_attn, qkv, M_ROWS, D3, D_MODEL);

    // Fused causal attention -> y
    dim3 ga(S_LEN / ATT_BQ, N_HEADS, BATCH);
    attn_kernel<<<ga, 256, attn_smem>>>(qkv, yb);

    // GEMM2: out = y @ w_proj^T   [8192 x 1024, K=1024]
    dim3 g2(D_MODEL / GBN, M_ROWS / GBM);
    gemm_nt<<<g2, 256>>>(yb, w_proj, out, M_ROWS, D_MODEL, D_MODEL);
}

// round 2
// speedup vs baseline: 1.9385x; 1.9385x over previous
#include <cuda_runtime.h>
#include <cstdint>
#include <cstddef>

// ---------------------------------------------------------------------------
// CausalSelfAttention: out = proj( causal_attn( x @ Wqkv^T ) )
// GEMMs on tensor cores (tf32 mma.sync m16n8k8), attention SIMT fp32 (for now)
// ---------------------------------------------------------------------------

#define BATCH   4
#define S_LEN   2048
#define D_MODEL 1024
#define D3      3072
#define N_HEADS 16
#define DH      64
#define M_ROWS  (BATCH * S_LEN)   // 8192

__device__ float g_qkv[(size_t)M_ROWS * D3];
__device__ float g_y[(size_t)M_ROWS * D_MODEL];

// ---------------------------------------------------------------------------
// tf32 tensor-core GEMM (NT): C[M,N] = A[M,K] @ B[N,K]^T, row-major, K contig.
// Block tile 128x128x16, 256 threads (8 warps in 2x4), warp tile 64x32.
// SMEM tiles stored [row][k] (16 floats/row) with 16B-chunk XOR swizzle:
//   chunk' = chunk ^ ((row>>1)&3)  -> conflict-free STS.128 and LDSM.
// Elements converted to tf32 (cvt.rna) at the global->shared store.
// ---------------------------------------------------------------------------
#define TBM 128
#define TBN 128
#define TBK 16

__device__ __forceinline__ int swz(int row, int k) {
    return row * TBK + ((((k >> 2) ^ ((row >> 1) & 3)) << 2) | (k & 3));
}

__device__ __forceinline__ uint32_t f2tf32(float f) {
    uint32_t r;
    asm("cvt.rna.tf32.f32 %0, %1;" : "=r"(r) : "f"(f));
    return r;
}

__device__ __forceinline__ void ldsm_x4(uint32_t addr, uint32_t& r0, uint32_t& r1,
                                        uint32_t& r2, uint32_t& r3) {
    asm volatile("ldmatrix.sync.aligned.m8n8.x4.shared.b16 {%0,%1,%2,%3}, [%4];"
                 : "=r"(r0), "=r"(r1), "=r"(r2), "=r"(r3) : "r"(addr));
}

__device__ __forceinline__ void mma_tf32(float& c0, float& c1, float& c2, float& c3,
                                         uint32_t a0, uint32_t a1, uint32_t a2, uint32_t a3,
                                         uint32_t b0, uint32_t b1) {
    asm volatile("mma.sync.aligned.m16n8k8.row.col.f32.tf32.tf32.f32 "
                 "{%0,%1,%2,%3}, {%4,%5,%6,%7}, {%8,%9}, {%0,%1,%2,%3};"
                 : "+f"(c0), "+f"(c1), "+f"(c2), "+f"(c3)
                 : "r"(a0), "r"(a1), "r"(a2), "r"(a3), "r"(b0), "r"(b1));
}

__global__ __launch_bounds__(256)
void gemm_tf32(const float* __restrict__ A, const float* __restrict__ B,
               float* __restrict__ C, int M, int N, int K) {
    __shared__ uint32_t As[2][TBM * TBK];
    __shared__ uint32_t Bs[2][TBN * TBK];

    const int tid    = threadIdx.x;
    const int lane   = tid & 31;
    const int warp   = tid >> 5;
    const int warp_m = warp >> 2;        // 0..1
    const int warp_n = warp & 3;         // 0..3
    const int row0   = blockIdx.y * TBM;
    const int col0   = blockIdx.x * TBN;

    // --- global load / shared store mapping (per thread: 2 float4 A, 2 B) ---
    // idx = tid + 256*r : row = idx>>2 (0..127), chunk = idx&3
    int g_row[2], g_chk[2];
#pragma unroll
    for (int r = 0; r < 2; r++) { int idx = tid + 256 * r; g_row[r] = idx >> 2; g_chk[r] = idx & 3; }

    const float* Ab = A + (size_t)row0 * K;
    const float* Bb = B + (size_t)col0 * K;

    // --- precompute LDSM shared addresses (byte offsets within a buffer) ---
    // A: per (mt 0..3, ks 0..1); mats: [m..m+7,k0..3][m+8..15,k0..3][m..m+7,k4..7][m+8..15,k4..7]
    uint32_t a_off[4][2], b_off[2][1 * 2];
    {
        int mat = lane >> 3, r = lane & 7;
#pragma unroll
        for (int mt = 0; mt < 4; mt++)
#pragma unroll
            for (int ks = 0; ks < 2; ks++) {
                int row = warp_m * 64 + mt * 16 + ((mat & 1) << 3) + r;
                int k   = ks * 8 + ((mat >> 1) << 2);
                a_off[mt][ks] = (uint32_t)(swz(row, k) * 4);
            }
        // B: per (ntp 0..1, ks): mats [n..n+7,k0..3][n..n+7,k4..7][n+8..15,k0..3][n+8..15,k4..7]
#pragma unroll
        for (int ntp = 0; ntp < 2; ntp++)
#pragma unroll
            for (int ks = 0; ks < 2; ks++) {
                int row = warp_n * 32 + ntp * 16 + ((mat >> 1) << 3) + r;
                int k   = ks * 8 + ((mat & 1) << 2);
                b_off[ntp][ks] = (uint32_t)(swz(row, k) * 4);
            }
    }
    uint32_t as_base[2], bs_base[2];
#pragma unroll
    for (int b = 0; b < 2; b++) {
        as_base[b] = (uint32_t)__cvta_generic_to_shared(&As[b][0]);
        bs_base[b] = (uint32_t)__cvta_generic_to_shared(&Bs[b][0]);
    }

    float c[4][4][4];
#pragma unroll
    for (int i = 0; i < 4; i++)
#pragma unroll
        for (int j = 0; j < 4; j++)
#pragma unroll
            for (int q = 0; q < 4; q++) c[i][j][q] = 0.f;

    const int NIT = K / TBK;
    float4 av[2], bv[2];

    // prologue: load tile 0
#pragma unroll
    for (int r = 0; r < 2; r++) {
        av[r] = *(const float4*)(Ab + (size_t)g_row[r] * K + g_chk[r] * 4);
        bv[r] = *(const float4*)(Bb + (size_t)g_row[r] * K + g_chk[r] * 4);
    }
#pragma unroll
    for (int r = 0; r < 2; r++) {
        int s = swz(g_row[r], g_chk[r] * 4);
        uint32_t* da = &As[0][s];
        da[0] = f2tf32(av[r].x); da[1] = f2tf32(av[r].y); da[2] = f2tf32(av[r].z); da[3] = f2tf32(av[r].w);
        uint32_t* db = &Bs[0][s];
        db[0] = f2tf32(bv[r].x); db[1] = f2tf32(bv[r].y); db[2] = f2tf32(bv[r].z); db[3] = f2tf32(bv[r].w);
    }
    __syncthreads();

    int buf = 0;
    for (int it = 0; it < NIT; it++) {
        const int k0 = (it + 1) * TBK;
        if (it + 1 < NIT) {
#pragma unroll
            for (int r = 0; r < 2; r++) {
                av[r] = *(const float4*)(Ab + (size_t)g_row[r] * K + k0 + g_chk[r] * 4);
                bv[r] = *(const float4*)(Bb + (size_t)g_row[r] * K + k0 + g_chk[r] * 4);
            }
        }

        // compute current tile
#pragma unroll
        for (int ks = 0; ks < 2; ks++) {
            uint32_t af[4][4];
#pragma unroll
            for (int mt = 0; mt < 4; mt++)
                ldsm_x4(as_base[buf] + a_off[mt][ks], af[mt][0], af[mt][1], af[mt][2], af[mt][3]);
            uint32_t bf[2][4];
#pragma unroll
            for (int ntp = 0; ntp < 2; ntp++)
                ldsm_x4(bs_base[buf] + b_off[ntp][ks], bf[ntp][0], bf[ntp][1], bf[ntp][2], bf[ntp][3]);
#pragma unroll
            for (int mt = 0; mt < 4; mt++)
#pragma unroll
                for (int nt = 0; nt < 4; nt++) {
                    const uint32_t* bp = &bf[nt >> 1][(nt & 1) * 2];
                    mma_tf32(c[mt][nt][0], c[mt][nt][1], c[mt][nt][2], c[mt][nt][3],
                             af[mt][0], af[mt][1], af[mt][2], af[mt][3], bp[0], bp[1]);
                }
        }

        if (it + 1 < NIT) {
            int nb = buf ^ 1;
#pragma unroll
            for (int r = 0; r < 2; r++) {
                int s = swz(g_row[r], g_chk[r] * 4);
                uint32_t* da = &As[nb][s];
                da[0] = f2tf32(av[r].x); da[1] = f2tf32(av[r].y); da[2] = f2tf32(av[r].z); da[3] = f2tf32(av[r].w);
                uint32_t* db = &Bs[nb][s];
                db[0] = f2tf32(bv[r].x); db[1] = f2tf32(bv[r].y); db[2] = f2tf32(bv[r].z); db[3] = f2tf32(bv[r].w);
            }
        }
        __syncthreads();
        buf ^= 1;
    }

    // epilogue: c0,c1 -> (row, 2c..2c+1); c2,c3 -> (row+8, ...)
    const int rql = lane >> 2;        // 0..7
    const int cpl = (lane & 3) * 2;   // 0,2,4,6
#pragma unroll
    for (int mt = 0; mt < 4; mt++) {
        int rg = row0 + warp_m * 64 + mt * 16 + rql;
#pragma unroll
        for (int nt = 0; nt < 4; nt++) {
            int cg = col0 + warp_n * 32 + nt * 8 + cpl;
            float2 v0 = {c[mt][nt][0], c[mt][nt][1]};
            float2 v1 = {c[mt][nt][2], c[mt][nt][3]};
            *(float2*)(C + (size_t)rg * N + cg)       = v0;
            *(float2*)(C + (size_t)(rg + 8) * N + cg) = v1;
        }
    }
}

// ---------------------------------------------------------------------------
// Fused causal flash attention (fp32 SIMT) — unchanged from R1.
// ---------------------------------------------------------------------------
#define ATT_BQ 128
#define ATT_BK 64

__global__ __launch_bounds__(256, 2)
void attn_kernel(const float* __restrict__ qkv, float* __restrict__ y) {
    extern __shared__ float sm[];
    float* Qs  = sm;
    float* Ps  = Qs + 128 * 65;
    float* Kst = Ps + 128 * 65;
    float* Vs  = Kst + 64 * 64;

    const int tid = threadIdx.x;
    const int tx  = tid & 7;
    const int ty  = tid >> 3;
    const int qi  = blockIdx.x;
    const int h   = blockIdx.y;
    const int b   = blockIdx.z;
    const int q0  = qi * ATT_BQ;

    const float* base = qkv + (size_t)b * S_LEN * D3;

#pragma unroll
    for (int r = 0; r < 8; r++) {
        int p   = tid + 256 * r;
        int row = p >> 4;
        int kq  = p & 15;
        float4 v = *(const float4*)(base + (size_t)(q0 + row) * D3 + h * DH + kq * 4);
        float* d = Qs + row * 65 + kq * 4;
        d[0] = v.x * 0.125f; d[1] = v.y * 0.125f; d[2] = v.z * 0.125f; d[3] = v.w * 0.125f;
    }

    float m[4], l[4], o[4][8];
#pragma unroll
    for (int i = 0; i < 4; i++) {
        m[i] = -1e30f; l[i] = 0.f;
#pragma unroll
        for (int j = 0; j < 8; j++) o[i][j] = 0.f;
    }

    const int njb = 2 * qi + 2;
    for (int jb = 0; jb < njb; jb++) {
        const int k0 = jb * ATT_BK;
        __syncthreads();

#pragma unroll
        for (int r = 0; r < 4; r++) {
            int p   = tid + 256 * r;
            int row = p >> 4;
            int kq  = p & 15;
            const float* gk = base + (size_t)(k0 + row) * D3 + D_MODEL + h * DH + kq * 4;
            float4 kv4 = *(const float4*)gk;
            Kst[(kq * 4 + 0) * 64 + row] = kv4.x;
            Kst[(kq * 4 + 1) * 64 + row] = kv4.y;
            Kst[(kq * 4 + 2) * 64 + row] = kv4.z;
            Kst[(kq * 4 + 3) * 64 + row] = kv4.w;
            const float* gv = base + (size_t)(k0 + row) * D3 + 2 * D_MODEL + h * DH + kq * 4;
            *(float4*)(Vs + row * 64 + kq * 4) = *(const float4*)gv;
        }
        __syncthreads();

        float s[4][8];
#pragma unroll
        for (int i = 0; i < 4; i++)
#pragma unroll
            for (int j = 0; j < 8; j++) s[i][j] = 0.f;

#pragma unroll 8
        for (int k = 0; k < 64; k++) {
            float a[4];
#pragma unroll
            for (int i = 0; i < 4; i++) a[i] = Qs[(ty * 4 + i) * 65 + k];
            float4 b0 = *(const float4*)(Kst + k * 64 + tx * 8);
            float4 b1 = *(const float4*)(Kst + k * 64 + tx * 8 + 4);
            float bb[8] = {b0.x, b0.y, b0.z, b0.w, b1.x, b1.y, b1.z, b1.w};
#pragma unroll
            for (int i = 0; i < 4; i++)
#pragma unroll
                for (int j = 0; j < 8; j++)
                    s[i][j] = fmaf(a[i], bb[j], s[i][j]);
        }

        if (k0 + ATT_BK - 1 > q0) {
#pragma unroll
            for (int i = 0; i < 4; i++) {
                int rg = q0 + ty * 4 + i;
#pragma unroll
                for (int j = 0; j < 8; j++) {
                    int cg = k0 + tx * 8 + j;
                    if (cg > rg) s[i][j] = -1e30f;
                }
            }
        }

#pragma unroll
        for (int i = 0; i < 4; i++) {
            float rmax = s[i][0];
#pragma unroll
            for (int j = 1; j < 8; j++) rmax = fmaxf(rmax, s[i][j]);
            rmax = fmaxf(rmax, __shfl_xor_sync(0xffffffffu, rmax, 1));
            rmax = fmaxf(rmax, __shfl_xor_sync(0xffffffffu, rmax, 2));
            rmax = fmaxf(rmax, __shfl_xor_sync(0xffffffffu, rmax, 4));
            float mnew  = fmaxf(m[i], rmax);
            float alpha = __expf(m[i] - mnew);
            m[i] = mnew;
            float rsum = 0.f;
#pragma unroll
            for (int j = 0; j < 8; j++) {
                float p = __expf(s[i][j] - mnew);
                s[i][j] = p;
                rsum += p;
            }
            rsum += __shfl_xor_sync(0xffffffffu, rsum, 1);
            rsum += __shfl_xor_sync(0xffffffffu, rsum, 2);
            rsum += __shfl_xor_sync(0xffffffffu, rsum, 4);
            l[i] = l[i] * alpha + rsum;
#pragma unroll
            for (int j = 0; j < 8; j++) o[i][j] *= alpha;
        }

#pragma unroll
        for (int i = 0; i < 4; i++) {
            float* pr = Ps + (ty * 4 + i) * 65 + tx * 8;
#pragma unroll
            for (int j = 0; j < 8; j++) pr[j] = s[i][j];
        }
        __syncthreads();

#pragma unroll 8
        for (int k = 0; k < 64; k++) {
            float a[4];
#pragma unroll
            for (int i = 0; i < 4; i++) a[i] = Ps[(ty * 4 + i) * 65 + k];
            float4 b0 = *(const float4*)(Vs + k * 64 + tx * 8);
            float4 b1 = *(const float4*)(Vs + k * 64 + tx * 8 + 4);
            float bb[8] = {b0.x, b0.y, b0.z, b0.w, b1.x, b1.y, b1.z, b1.w};
#pragma unroll
            for (int i = 0; i < 4; i++)
#pragma unroll
                for (int j = 0; j < 8; j++)
                    o[i][j] = fmaf(a[i], bb[j], o[i][j]);
        }
    }

#pragma unroll
    for (int i = 0; i < 4; i++) {
        float inv = 1.0f / l[i];
        int rg = q0 + ty * 4 + i;
        float* yr = y + ((size_t)b * S_LEN + rg) * D_MODEL + h * DH + tx * 8;
        float4 v0 = {o[i][0] * inv, o[i][1] * inv, o[i][2] * inv, o[i][3] * inv};
        float4 v1 = {o[i][4] * inv, o[i][5] * inv, o[i][6] * inv, o[i][7] * inv};
        *(float4*)(yr)     = v0;
        *(float4*)(yr + 4) = v1;
    }
}

// ---------------------------------------------------------------------------
extern "C" void kernel_launch(void* const* d_in, const int* in_sizes, int n_in,
                              void* d_out, int out_size) {
    const float* x      = (const float*)d_in[0];
    const float* w_attn = (const float*)d_in[1];
    const float* w_proj = (const float*)d_in[2];
    float* out = (float*)d_out;

    float *qkv = nullptr, *yb = nullptr;
    cudaGetSymbolAddress((void**)&qkv, g_qkv);
    cudaGetSymbolAddress((void**)&yb, g_y);

    const int attn_smem = (128 * 65 * 2 + 64 * 64 * 2) * (int)sizeof(float);
    cudaFuncSetAttribute(attn_kernel, cudaFuncAttributeMaxDynamicSharedMemorySize, attn_smem);

    // GEMM1: qkv = x @ w_attn^T   [8192 x 3072, K=1024]
    dim3 g1(D3 / TBN, M_ROWS / TBM);
    gemm_tf32<<<g1, 256>>>(x, w_attn, qkv, M_ROWS, D3, D_MODEL);

    // Fused causal attention -> y
    dim3 ga(S_LEN / ATT_BQ, N_HEADS, BATCH);
    attn_kernel<<<ga, 256, attn_smem>>>(qkv, yb);

    // GEMM2: out = y @ w_proj^T   [8192 x 1024, K=1024]
    dim3 g2(D_MODEL / TBN, M_ROWS / TBM);
    gemm_tf32<<<g2, 256>>>(yb, w_proj, out, M_ROWS, D_MODEL, D_MODEL);
}

// round 3
// speedup vs baseline: 4.8022x; 2.4773x over previous
#include <cuda_runtime.h>
#include <cstdint>
#include <cstddef>

// ---------------------------------------------------------------------------
// CausalSelfAttention: out = proj( causal_attn( x @ Wqkv^T ) )
// All three matmul stages on tensor cores (tf32 mma.sync m16n8k8).
// ---------------------------------------------------------------------------

#define BATCH   4
#define S_LEN   2048
#define D_MODEL 1024
#define D3      3072
#define N_HEADS 16
#define DH      64
#define M_ROWS  (BATCH * S_LEN)   // 8192

__device__ float g_qkv[(size_t)M_ROWS * D3];
__device__ float g_y[(size_t)M_ROWS * D_MODEL];
__device__ float g_vt[(size_t)BATCH * N_HEADS * DH * S_LEN];  // V^T: [b][h][d][s]

// ---- common tf32 helpers ---------------------------------------------------
__device__ __forceinline__ uint32_t f2tf32(float f) {
    uint32_t r;
    asm("cvt.rna.tf32.f32 %0, %1;" : "=r"(r) : "f"(f));
    return r;
}
__device__ __forceinline__ float ex2f(float x) {
    float r;
    asm("ex2.approx.ftz.f32 %0, %1;" : "=f"(r) : "f"(x));
    return r;
}
__device__ __forceinline__ void ldsm_x4(uint32_t addr, uint32_t& r0, uint32_t& r1,
                                        uint32_t& r2, uint32_t& r3) {
    asm volatile("ldmatrix.sync.aligned.m8n8.x4.shared.b16 {%0,%1,%2,%3}, [%4];"
                 : "=r"(r0), "=r"(r1), "=r"(r2), "=r"(r3) : "r"(addr));
}
__device__ __forceinline__ void mma_tf32(float& c0, float& c1, float& c2, float& c3,
                                         uint32_t a0, uint32_t a1, uint32_t a2, uint32_t a3,
                                         uint32_t b0, uint32_t b1) {
    asm volatile("mma.sync.aligned.m16n8k8.row.col.f32.tf32.tf32.f32 "
                 "{%0,%1,%2,%3}, {%4,%5,%6,%7}, {%8,%9}, {%0,%1,%2,%3};"
                 : "+f"(c0), "+f"(c1), "+f"(c2), "+f"(c3)
                 : "r"(a0), "r"(a1), "r"(a2), "r"(a3), "r"(b0), "r"(b1));
}

// ---------------------------------------------------------------------------
// tf32 GEMM (NT): C[M,N] = A[M,K] @ B[N,K]^T  (unchanged from R2)
// ---------------------------------------------------------------------------
#define TBM 128
#define TBN 128
#define TBK 16

__device__ __forceinline__ int swz(int row, int k) {
    return row * TBK + ((((k >> 2) ^ ((row >> 1) & 3)) << 2) | (k & 3));
}

__global__ __launch_bounds__(256)
void gemm_tf32(const float* __restrict__ A, const float* __restrict__ B,
               float* __restrict__ C, int M, int N, int K) {
    __shared__ uint32_t As[2][TBM * TBK];
    __shared__ uint32_t Bs[2][TBN * TBK];

    const int tid    = threadIdx.x;
    const int lane   = tid & 31;
    const int warp   = tid >> 5;
    const int warp_m = warp >> 2;
    const int warp_n = warp & 3;
    const int row0   = blockIdx.y * TBM;
    const int col0   = blockIdx.x * TBN;

    int g_row[2], g_chk[2];
#pragma unroll
    for (int r = 0; r < 2; r++) { int idx = tid + 256 * r; g_row[r] = idx >> 2; g_chk[r] = idx & 3; }

    const float* Ab = A + (size_t)row0 * K;
    const float* Bb = B + (size_t)col0 * K;

    uint32_t a_off[4][2], b_off[2][2];
    {
        int mat = lane >> 3, r = lane & 7;
#pragma unroll
        for (int mt = 0; mt < 4; mt++)
#pragma unroll
            for (int ks = 0; ks < 2; ks++) {
                int row = warp_m * 64 + mt * 16 + ((mat & 1) << 3) + r;
                int k   = ks * 8 + ((mat >> 1) << 2);
                a_off[mt][ks] = (uint32_t)(swz(row, k) * 4);
            }
#pragma unroll
        for (int ntp = 0; ntp < 2; ntp++)
#pragma unroll
            for (int ks = 0; ks < 2; ks++) {
                int row = warp_n * 32 + ntp * 16 + ((mat >> 1) << 3) + r;
                int k   = ks * 8 + ((mat & 1) << 2);
                b_off[ntp][ks] = (uint32_t)(swz(row, k) * 4);
            }
    }
    uint32_t as_base[2], bs_base[2];
#pragma unroll
    for (int b = 0; b < 2; b++) {
        as_base[b] = (uint32_t)__cvta_generic_to_shared(&As[b][0]);
        bs_base[b] = (uint32_t)__cvta_generic_to_shared(&Bs[b][0]);
    }

    float c[4][4][4];
#pragma unroll
    for (int i = 0; i < 4; i++)
#pragma unroll
        for (int j = 0; j < 4; j++)
#pragma unroll
            for (int q = 0; q < 4; q++) c[i][j][q] = 0.f;

    const int NIT = K / TBK;
    float4 av[2], bv[2];

#pragma unroll
    for (int r = 0; r < 2; r++) {
        av[r] = *(const float4*)(Ab + (size_t)g_row[r] * K + g_chk[r] * 4);
        bv[r] = *(const float4*)(Bb + (size_t)g_row[r] * K + g_chk[r] * 4);
    }
#pragma unroll
    for (int r = 0; r < 2; r++) {
        int s = swz(g_row[r], g_chk[r] * 4);
        uint32_t* da = &As[0][s];
        da[0] = f2tf32(av[r].x); da[1] = f2tf32(av[r].y); da[2] = f2tf32(av[r].z); da[3] = f2tf32(av[r].w);
        uint32_t* db = &Bs[0][s];
        db[0] = f2tf32(bv[r].x); db[1] = f2tf32(bv[r].y); db[2] = f2tf32(bv[r].z); db[3] = f2tf32(bv[r].w);
    }
    __syncthreads();

    int buf = 0;
    for (int it = 0; it < NIT; it++) {
        const int k0 = (it + 1) * TBK;
        if (it + 1 < NIT) {
#pragma unroll
            for (int r = 0; r < 2; r++) {
                av[r] = *(const float4*)(Ab + (size_t)g_row[r] * K + k0 + g_chk[r] * 4);
                bv[r] = *(const float4*)(Bb + (size_t)g_row[r] * K + k0 + g_chk[r] * 4);
            }
        }

#pragma unroll
        for (int ks = 0; ks < 2; ks++) {
            uint32_t af[4][4];
#pragma unroll
            for (int mt = 0; mt < 4; mt++)
                ldsm_x4(as_base[buf] + a_off[mt][ks], af[mt][0], af[mt][1], af[mt][2], af[mt][3]);
            uint32_t bf[2][4];
#pragma unroll
            for (int ntp = 0; ntp < 2; ntp++)
                ldsm_x4(bs_base[buf] + b_off[ntp][ks], bf[ntp][0], bf[ntp][1], bf[ntp][2], bf[ntp][3]);
#pragma unroll
            for (int mt = 0; mt < 4; mt++)
#pragma unroll
                for (int nt = 0; nt < 4; nt++) {
                    const uint32_t* bp = &bf[nt >> 1][(nt & 1) * 2];
                    mma_tf32(c[mt][nt][0], c[mt][nt][1], c[mt][nt][2], c[mt][nt][3],
                             af[mt][0], af[mt][1], af[mt][2], af[mt][3], bp[0], bp[1]);
                }
        }

        if (it + 1 < NIT) {
            int nb = buf ^ 1;
#pragma unroll
            for (int r = 0; r < 2; r++) {
                int s = swz(g_row[r], g_chk[r] * 4);
                uint32_t* da = &As[nb][s];
                da[0] = f2tf32(av[r].x); da[1] = f2tf32(av[r].y); da[2] = f2tf32(av[r].z); da[3] = f2tf32(av[r].w);
                uint32_t* db = &Bs[nb][s];
                db[0] = f2tf32(bv[r].x); db[1] = f2tf32(bv[r].y); db[2] = f2tf32(bv[r].z); db[3] = f2tf32(bv[r].w);
            }
        }
        __syncthreads();
        buf ^= 1;
    }

    const int rql = lane >> 2;
    const int cpl = (lane & 3) * 2;
#pragma unroll
    for (int mt = 0; mt < 4; mt++) {
        int rg = row0 + warp_m * 64 + mt * 16 + rql;
#pragma unroll
        for (int nt = 0; nt < 4; nt++) {
            int cg = col0 + warp_n * 32 + nt * 8 + cpl;
            float2 v0 = {c[mt][nt][0], c[mt][nt][1]};
            float2 v1 = {c[mt][nt][2], c[mt][nt][3]};
            *(float2*)(C + (size_t)rg * N + cg)       = v0;
            *(float2*)(C + (size_t)(rg + 8) * N + cg) = v1;
        }
    }
}

// ---------------------------------------------------------------------------
// V transpose: g_vt[b][h][d][s] = qkv[b][s][2*D + h*64 + d]
// ---------------------------------------------------------------------------
__global__ __launch_bounds__(256)
void vtrans(const float* __restrict__ qkv, float* __restrict__ vt) {
    __shared__ float t[32][33];
    const int bh = blockIdx.z;           // b*16 + h
    const int b  = bh >> 4, h = bh & 15;
    const int s0 = blockIdx.x * 32;
    const int d0 = blockIdx.y * 32;
    const int txx = threadIdx.x, tyy = threadIdx.y;

#pragma unroll
    for (int i = tyy; i < 32; i += 8)
        t[i][txx] = qkv[((size_t)(b * S_LEN) + s0 + i) * D3 + 2 * D_MODEL + h * DH + d0 + txx];
    __syncthreads();
#pragma unroll
    for (int i = tyy; i < 32; i += 8)
        vt[((size_t)bh * DH + d0 + i) * S_LEN + s0 + txx] = t[txx][i];
}

// ---------------------------------------------------------------------------
// Tensor-core causal flash attention.
// Block: 128 q-rows x 64 kv per iter, 8 warps (warp = 16 q-rows x 64 kv).
// SMEM rows of 64 tf32 values, 16B-chunk xor swizzle: chunk' = chunk^(row&7).
// ---------------------------------------------------------------------------
#define AQ_SWZ(row, k) ((row) * 64 + ((((k) >> 2) ^ ((row) & 7)) << 2) + ((k) & 3))
#define ATT_SCALE 0.18033688f   /* 0.125 * log2(e) */

__global__ __launch_bounds__(256)
void attn_tc(const float* __restrict__ qkv, const float* __restrict__ vt,
             float* __restrict__ y) {
    extern __shared__ uint32_t smu[];
    uint32_t* Qs = smu;            // 128*64
    uint32_t* Ks = Qs + 8192;      // 2 * 64*64
    uint32_t* Vs = Ks + 8192;      // 2 * 64*64

    const int tid  = threadIdx.x;
    const int lane = tid & 31;
    const int w    = tid >> 5;
    const int qi   = (S_LEN / 128 - 1) - blockIdx.x;   // heavy tiles first
    const int h    = blockIdx.y;
    const int b    = blockIdx.z;
    const int q0   = qi * 128;

    const float* qb = qkv + (size_t)b * S_LEN * D3 + h * DH;
    const float* kb = qb + D_MODEL;
    const float* vb = vt + ((size_t)(b * N_HEADS + h)) * DH * S_LEN;

    const uint32_t qs_base = (uint32_t)__cvta_generic_to_shared(Qs);
    const uint32_t ks_base = (uint32_t)__cvta_generic_to_shared(Ks);
    const uint32_t vs_base = (uint32_t)__cvta_generic_to_shared(Vs);

    // cooperative tile-load mapping: idx -> (row = idx>>4, chunk = idx&15)
    int l_row[4], l_chk[4];
#pragma unroll
    for (int r = 0; r < 4; r++) { int idx = tid + 256 * r; l_row[r] = idx >> 4; l_chk[r] = idx & 15; }

    // ---- prologue: load Q (scaled) + K/V tile 0 ----
#pragma unroll
    for (int r = 0; r < 8; r++) {
        int idx = tid + 256 * r, row = idx >> 4, ch = idx & 15;
        float4 v = *(const float4*)(qb + (size_t)(q0 + row) * D3 + ch * 4);
        uint32_t* d = &Qs[AQ_SWZ(row, ch * 4)];
        d[0] = f2tf32(v.x * ATT_SCALE); d[1] = f2tf32(v.y * ATT_SCALE);
        d[2] = f2tf32(v.z * ATT_SCALE); d[3] = f2tf32(v.w * ATT_SCALE);
    }
#pragma unroll
    for (int r = 0; r < 4; r++) {
        int row = l_row[r], ch = l_chk[r];
        float4 kv4 = *(const float4*)(kb + (size_t)row * D3 + ch * 4);
        uint32_t* dk = &Ks[AQ_SWZ(row, ch * 4)];
        dk[0] = f2tf32(kv4.x); dk[1] = f2tf32(kv4.y); dk[2] = f2tf32(kv4.z); dk[3] = f2tf32(kv4.w);
        float4 vv4 = *(const float4*)(vb + (size_t)row * S_LEN + ch * 4);
        uint32_t* dv = &Vs[AQ_SWZ(row, ch * 4)];
        dv[0] = f2tf32(vv4.x); dv[1] = f2tf32(vv4.y); dv[2] = f2tf32(vv4.z); dv[3] = f2tf32(vv4.w);
    }
    __syncthreads();

    // ---- Q fragments (loop-invariant): qf[ks][4] ----
    const int mat = lane >> 3, rr = lane & 7;
    uint32_t qf[8][4];
    {
        int rowA = w * 16 + ((mat & 1) << 3) + rr;
        int rbase = rowA * 256;            // bytes
        int rx = rowA & 7;
#pragma unroll
        for (int ks = 0; ks < 8; ks++) {
            int kc = ks * 2 + (mat >> 1);
            ldsm_x4(qs_base + rbase + (((kc ^ rx)) << 4), qf[ks][0], qf[ks][1], qf[ks][2], qf[ks][3]);
        }
    }
    // B-side (K and V) ldsm per-lane constants
    uint32_t browOff[4]; int brx[4];
#pragma unroll
    for (int ntp = 0; ntp < 4; ntp++) {
        int rowB = ntp * 16 + ((mat >> 1) << 3) + rr;
        browOff[ntp] = (uint32_t)(rowB * 256);
        brx[ntp] = rowB & 7;
    }
    const int kbit = mat & 1;

    float m_lo = -1e30f, m_hi = -1e30f, l_lo = 0.f, l_hi = 0.f;
    float co[8][4];
#pragma unroll
    for (int i = 0; i < 8; i++)
#pragma unroll
        for (int q = 0; q < 4; q++) co[i][q] = 0.f;

    const int rlo = q0 + w * 16 + (lane >> 2);
    const int jsel = lane & 3;
    const int src0 = (lane & 28) | (jsel >> 1);

    const int njb = 2 * qi + 2;
    int buf = 0;
    float4 kst[4], vst[4];

    for (int jb = 0; jb < njb; jb++) {
        // issue next-tile global loads
        if (jb + 1 < njb) {
            const int kn = (jb + 1) * 64;
#pragma unroll
            for (int r = 0; r < 4; r++) {
                kst[r] = *(const float4*)(kb + (size_t)(kn + l_row[r]) * D3 + l_chk[r] * 4);
                vst[r] = *(const float4*)(vb + (size_t)l_row[r] * S_LEN + kn + l_chk[r] * 4);
            }
        }

        const uint32_t kbuf = ks_base + (uint32_t)(buf * 16384);
        const uint32_t vbuf = vs_base + (uint32_t)(buf * 16384);

        // ---- S = Q @ K^T ----
        float cs[8][4];
#pragma unroll
        for (int i = 0; i < 8; i++)
#pragma unroll
            for (int q = 0; q < 4; q++) cs[i][q] = 0.f;

#pragma unroll
        for (int ks = 0; ks < 8; ks++) {
            uint32_t bf[4][4];
            int kc = ks * 2 + kbit;
#pragma unroll
            for (int ntp = 0; ntp < 4; ntp++)
                ldsm_x4(kbuf + browOff[ntp] + (((kc ^ brx[ntp])) << 4),
                        bf[ntp][0], bf[ntp][1], bf[ntp][2], bf[ntp][3]);
#pragma unroll
            for (int nt = 0; nt < 8; nt++) {
                const uint32_t* bp = &bf[nt >> 1][(nt & 1) * 2];
                mma_tf32(cs[nt][0], cs[nt][1], cs[nt][2], cs[nt][3],
                         qf[ks][0], qf[ks][1], qf[ks][2], qf[ks][3], bp[0], bp[1]);
            }
        }

        // ---- causal mask (last two tiles only) ----
        if (jb * 64 >= q0) {
#pragma unroll
            for (int nt = 0; nt < 8; nt++) {
                int cb = jb * 64 + nt * 8 + 2 * jsel;
                if (cb     > rlo)     cs[nt][0] = -1e30f;
                if (cb + 1 > rlo)     cs[nt][1] = -1e30f;
                if (cb     > rlo + 8) cs[nt][2] = -1e30f;
                if (cb + 1 > rlo + 8) cs[nt][3] = -1e30f;
            }
        }

        // ---- online softmax (base-2 domain) ----
        float ml = -1e30f, mh = -1e30f;
#pragma unroll
        for (int nt = 0; nt < 8; nt++) {
            ml = fmaxf(ml, fmaxf(cs[nt][0], cs[nt][1]));
            mh = fmaxf(mh, fmaxf(cs[nt][2], cs[nt][3]));
        }
        ml = fmaxf(ml, __shfl_xor_sync(0xffffffffu, ml, 1));
        ml = fmaxf(ml, __shfl_xor_sync(0xffffffffu, ml, 2));
        mh = fmaxf(mh, __shfl_xor_sync(0xffffffffu, mh, 1));
        mh = fmaxf(mh, __shfl_xor_sync(0xffffffffu, mh, 2));
        float Ml = fmaxf(m_lo, ml), Mh = fmaxf(m_hi, mh);
        float al = ex2f(m_lo - Ml), ah = ex2f(m_hi - Mh);
        m_lo = Ml; m_hi = Mh;

        float sl = 0.f, sh = 0.f;
#pragma unroll
        for (int nt = 0; nt < 8; nt++) {
            cs[nt][0] = ex2f(cs[nt][0] - Ml);
            cs[nt][1] = ex2f(cs[nt][1] - Ml);
            cs[nt][2] = ex2f(cs[nt][2] - Mh);
            cs[nt][3] = ex2f(cs[nt][3] - Mh);
            sl += cs[nt][0] + cs[nt][1];
            sh += cs[nt][2] + cs[nt][3];
        }
        sl += __shfl_xor_sync(0xffffffffu, sl, 1);
        sl += __shfl_xor_sync(0xffffffffu, sl, 2);
        sh += __shfl_xor_sync(0xffffffffu, sh, 1);
        sh += __shfl_xor_sync(0xffffffffu, sh, 2);
        l_lo = l_lo * al + sl;
        l_hi = l_hi * ah + sh;
#pragma unroll
        for (int i = 0; i < 8; i++) {
            co[i][0] *= al; co[i][1] *= al; co[i][2] *= ah; co[i][3] *= ah;
        }

        // ---- O += P @ V  (re-fragment P via quad shuffles) ----
#pragma unroll
        for (int kt = 0; kt < 8; kt++) {
            float v00 = __shfl_sync(0xffffffffu, cs[kt][0], src0);
            float v01 = __shfl_sync(0xffffffffu, cs[kt][1], src0);
            float v20 = __shfl_sync(0xffffffffu, cs[kt][0], src0 + 2);
            float v21 = __shfl_sync(0xffffffffu, cs[kt][1], src0 + 2);
            float v10 = __shfl_sync(0xffffffffu, cs[kt][2], src0);
            float v11 = __shfl_sync(0xffffffffu, cs[kt][3], src0);
            float v30 = __shfl_sync(0xffffffffu, cs[kt][2], src0 + 2);
            float v31 = __shfl_sync(0xffffffffu, cs[kt][3], src0 + 2);
            uint32_t pa0 = f2tf32((jsel & 1) ? v01 : v00);
            uint32_t pa1 = f2tf32((jsel & 1) ? v11 : v10);
            uint32_t pa2 = f2tf32((jsel & 1) ? v21 : v20);
            uint32_t pa3 = f2tf32((jsel & 1) ? v31 : v30);

            uint32_t bf[4];
            int kc = kt * 2 + kbit;
#pragma unroll
            for (int ntp = 0; ntp < 4; ntp++) {
                ldsm_x4(vbuf + browOff[ntp] + (((kc ^ brx[ntp])) << 4),
                        bf[0], bf[1], bf[2], bf[3]);
                mma_tf32(co[2 * ntp][0], co[2 * ntp][1], co[2 * ntp][2], co[2 * ntp][3],
                         pa0, pa1, pa2, pa3, bf[0], bf[1]);
                mma_tf32(co[2 * ntp + 1][0], co[2 * ntp + 1][1], co[2 * ntp + 1][2], co[2 * ntp + 1][3],
                         pa0, pa1, pa2, pa3, bf[2], bf[3]);
            }
        }

        // store staged next tile
        if (jb + 1 < njb) {
            uint32_t* Kn = Ks + (buf ^ 1) * 4096;
            uint32_t* Vn = Vs + (buf ^ 1) * 4096;
#pragma unroll
            for (int r = 0; r < 4; r++) {
                int s = AQ_SWZ(l_row[r], l_chk[r] * 4);
                uint32_t* dk = &Kn[s];
                dk[0] = f2tf32(kst[r].x); dk[1] = f2tf32(kst[r].y);
                dk[2] = f2tf32(kst[r].z); dk[3] = f2tf32(kst[r].w);
                uint32_t* dv = &Vn[s];
                dv[0] = f2tf32(vst[r].x); dv[1] = f2tf32(vst[r].y);
                dv[2] = f2tf32(vst[r].z); dv[3] = f2tf32(vst[r].w);
            }
        }
        __syncthreads();
        buf ^= 1;
    }

    // ---- epilogue: y[b, row, h*64 + col] = O / l ----
    const float il = 1.0f / l_lo, ih = 1.0f / l_hi;
    float* yb = y + ((size_t)b * S_LEN + q0 + w * 16 + (lane >> 2)) * D_MODEL + h * DH + 2 * jsel;
#pragma unroll
    for (int nt = 0; nt < 8; nt++) {
        float2 v0 = {co[nt][0] * il, co[nt][1] * il};
        float2 v1 = {co[nt][2] * ih, co[nt][3] * ih};
        *(float2*)(yb + nt * 8)                       = v0;
        *(float2*)(yb + nt * 8 + 8 * (size_t)D_MODEL) = v1;
    }
}

// ---------------------------------------------------------------------------
extern "C" void kernel_launch(void* const* d_in, const int* in_sizes, int n_in,
                              void* d_out, int out_size) {
    const float* x      = (const float*)d_in[0];
    const float* w_attn = (const float*)d_in[1];
    const float* w_proj = (const float*)d_in[2];
    float* out = (float*)d_out;

    float *qkv = nullptr, *yb = nullptr, *vt = nullptr;
    cudaGetSymbolAddress((void**)&qkv, g_qkv);
    cudaGetSymbolAddress((void**)&yb, g_y);
    cudaGetSymbolAddress((void**)&vt, g_vt);

    const int attn_smem = 98304;  // Qs 32K + K 2x16K + V 2x16K
    cudaFuncSetAttribute(attn_tc, cudaFuncAttributeMaxDynamicSharedMemorySize, attn_smem);

    // GEMM1: qkv = x @ w_attn^T
    dim3 g1(D3 / TBN, M_ROWS / TBM);
    gemm_tf32<<<g1, 256>>>(x, w_attn, qkv, M_ROWS, D3, D_MODEL);

    // V transpose
    dim3 gt(S_LEN / 32, DH / 32, BATCH * N_HEADS);
    vtrans<<<gt, dim3(32, 8)>>>(qkv, vt);

    // Tensor-core causal attention
    dim3 ga(S_LEN / 128, N_HEADS, BATCH);
    attn_tc<<<ga, 256, attn_smem>>>(qkv, vt, yb);

    // GEMM2: out = y @ w_proj^T
    dim3 g2(D_MODEL / TBN, M_ROWS / TBM);
    gemm_tf32<<<g2, 256>>>(yb, w_proj, out, M_ROWS, D_MODEL, D_MODEL);
}

// round 4
// speedup vs baseline: 6.0246x; 1.2545x over previous
#include <cuda_runtime.h>
#include <cstdint>
#include <cstddef>

// ---------------------------------------------------------------------------
// CausalSelfAttention: out = proj( causal_attn( x @ Wqkv^T ) )
// tf32 mma.sync everywhere; operands pre-rounded to tf32 bits so mainloops
// carry zero conversion work; cp.async multi-stage pipelines.
// ---------------------------------------------------------------------------

#define BATCH   4
#define S_LEN   2048
#define D_MODEL 1024
#define D3      3072
#define N_HEADS 16
#define DH      64
#define M_ROWS  (BATCH * S_LEN)   // 8192

__device__ float g_qkv[(size_t)M_ROWS * D3];
__device__ float g_y[(size_t)M_ROWS * D_MODEL];
__device__ float g_vt[(size_t)BATCH * N_HEADS * DH * S_LEN];
__device__ float g_xc[(size_t)M_ROWS * D_MODEL];     // x rounded to tf32
__device__ float g_wac[(size_t)D3 * D_MODEL];        // w_attn rounded
__device__ float g_wpc[(size_t)D_MODEL * D_MODEL];   // w_proj rounded

// ---- helpers ----------------------------------------------------------------
__device__ __forceinline__ uint32_t f2tf32(float f) {
    uint32_t r;
    asm("cvt.rna.tf32.f32 %0, %1;" : "=r"(r) : "f"(f));
    return r;
}
__device__ __forceinline__ float ex2f(float x) {
    float r;
    asm("ex2.approx.ftz.f32 %0, %1;" : "=f"(r) : "f"(x));
    return r;
}
__device__ __forceinline__ void ldsm_x4(uint32_t addr, uint32_t& r0, uint32_t& r1,
                                        uint32_t& r2, uint32_t& r3) {
    asm volatile("ldmatrix.sync.aligned.m8n8.x4.shared.b16 {%0,%1,%2,%3}, [%4];"
                 : "=r"(r0), "=r"(r1), "=r"(r2), "=r"(r3) : "r"(addr));
}
__device__ __forceinline__ void mma_tf32(float& c0, float& c1, float& c2, float& c3,
                                         uint32_t a0, uint32_t a1, uint32_t a2, uint32_t a3,
                                         uint32_t b0, uint32_t b1) {
    asm volatile("mma.sync.aligned.m16n8k8.row.col.f32.tf32.tf32.f32 "
                 "{%0,%1,%2,%3}, {%4,%5,%6,%7}, {%8,%9}, {%0,%1,%2,%3};"
                 : "+f"(c0), "+f"(c1), "+f"(c2), "+f"(c3)
                 : "r"(a0), "r"(a1), "r"(a2), "r"(a3), "r"(b0), "r"(b1));
}
__device__ __forceinline__ void cp16(uint32_t dst, const void* src) {
    asm volatile("cp.async.cg.shared.global [%0], [%1], 16;" :: "r"(dst), "l"(src));
}
#define CP_COMMIT() asm volatile("cp.async.commit_group;")
#define CP_WAIT(n)  asm volatile("cp.async.wait_group %0;" :: "n"(n))

// ---------------------------------------------------------------------------
// Pre-round fp32 -> tf32-bits (stored as float)
// ---------------------------------------------------------------------------
__global__ void round_tf32(const float* __restrict__ in, float* __restrict__ out, int n4) {
    int i = blockIdx.x * blockDim.x + threadIdx.x;
    if (i < n4) {
        float4 v = ((const float4*)in)[i];
        uint4 r = {f2tf32(v.x), f2tf32(v.y), f2tf32(v.z), f2tf32(v.w)};
        ((uint4*)out)[i] = r;
    }
}

// ---------------------------------------------------------------------------
// tf32 GEMM (NT), cp.async 3-stage: C[M,N] = A[M,K] @ B[N,K]^T
// A,B already tf32-rounded. ROUND: round outputs to tf32 bits.
// Block 128x128x16, 8 warps (2x4), warp tile 64x32.
// ---------------------------------------------------------------------------
#define TBM 128
#define TBN 128
#define TBK 16
#define GSTG 3

__device__ __forceinline__ int swz(int row, int k) {
    return row * TBK + ((((k >> 2) ^ ((row >> 1) & 3)) << 2) | (k & 3));
}

template <bool ROUND>
__global__ __launch_bounds__(256)
void gemm_tf32_cp(const float* __restrict__ A, const float* __restrict__ B,
                  float* __restrict__ C, int M, int N, int K) {
    extern __shared__ uint32_t sh[];   // GSTG*(2048 A + 2048 B) u32 = 49152 B

    const int tid    = threadIdx.x;
    const int lane   = tid & 31;
    const int warp   = tid >> 5;
    const int warp_m = warp >> 2;
    const int warp_n = warp & 3;
    const int row0   = blockIdx.y * TBM;
    const int col0   = blockIdx.x * TBN;

    const float* Ab = A + (size_t)row0 * K;
    const float* Bb = B + (size_t)col0 * K;

    // per-thread cp.async mapping: 2 chunks A, 2 chunks B
    const float* a_src[2];
    const float* b_src[2];
    uint32_t a_dst[2], b_dst[2];
    {
        uint32_t base = (uint32_t)__cvta_generic_to_shared(sh);
#pragma unroll
        for (int r = 0; r < 2; r++) {
            int idx = tid + 256 * r, row = idx >> 2, ch = idx & 3;
            a_src[r] = Ab + (size_t)row * K + ch * 4;
            b_src[r] = Bb + (size_t)row * K + ch * 4;
            a_dst[r] = base + (uint32_t)(swz(row, ch * 4) * 4);
            b_dst[r] = base + (uint32_t)(GSTG * 8192 + swz(row, ch * 4) * 4);
        }
    }
    uint32_t sA[GSTG], sB[GSTG];
    {
        uint32_t base = (uint32_t)__cvta_generic_to_shared(sh);
#pragma unroll
        for (int s = 0; s < GSTG; s++) { sA[s] = base + s * 8192; sB[s] = base + GSTG * 8192 + s * 8192; }
    }

    // ldsm offsets (bytes within a stage)
    uint32_t a_off[4][2], b_off[2][2];
    {
        int mat = lane >> 3, r = lane & 7;
#pragma unroll
        for (int mt = 0; mt < 4; mt++)
#pragma unroll
            for (int ks = 0; ks < 2; ks++) {
                int row = warp_m * 64 + mt * 16 + ((mat & 1) << 3) + r;
                int k   = ks * 8 + ((mat >> 1) << 2);
                a_off[mt][ks] = (uint32_t)(swz(row, k) * 4);
            }
#pragma unroll
        for (int ntp = 0; ntp < 2; ntp++)
#pragma unroll
            for (int ks = 0; ks < 2; ks++) {
                int row = warp_n * 32 + ntp * 16 + ((mat >> 1) << 3) + r;
                int k   = ks * 8 + ((mat & 1) << 2);
                b_off[ntp][ks] = (uint32_t)(swz(row, k) * 4);
            }
    }

    float c[4][4][4];
#pragma unroll
    for (int i = 0; i < 4; i++)
#pragma unroll
        for (int j = 0; j < 4; j++)
#pragma unroll
            for (int q = 0; q < 4; q++) c[i][j][q] = 0.f;

    const int NIT = K / TBK;

#define G_ISSUE(s, k0)                                             \
    do {                                                           \
        _Pragma("unroll")                                          \
        for (int r = 0; r < 2; r++) {                              \
            cp16(sA[s] + a_dst[r] - sA[0] + sA[s] - sA[s], a_src[r] + (k0)); \
            cp16(sB[s] + (b_dst[r] - (sB[0])), b_src[r] + (k0));   \
        }                                                          \
    } while (0)

    // (the macro above would be convoluted; do it inline instead)
#undef G_ISSUE

    // stage-relative dst offsets
    uint32_t a_rel[2], b_rel[2];
#pragma unroll
    for (int r = 0; r < 2; r++) { a_rel[r] = a_dst[r] - sA[0]; b_rel[r] = b_dst[r] - sB[0]; }

    // prologue: stages 0,1
#pragma unroll
    for (int s = 0; s < 2; s++) {
#pragma unroll
        for (int r = 0; r < 2; r++) {
            cp16(sA[s] + a_rel[r], a_src[r] + s * TBK);
            cp16(sB[s] + b_rel[r], b_src[r] + s * TBK);
        }
        CP_COMMIT();
    }
    CP_WAIT(1);
    __syncthreads();

    int buf = 0, nxt = 2;
    for (int it = 0; it < NIT; it++) {
        if (it + 2 < NIT) {
            const int k0 = (it + 2) * TBK;
#pragma unroll
            for (int r = 0; r < 2; r++) {
                cp16(sA[nxt] + a_rel[r], a_src[r] + k0);
                cp16(sB[nxt] + b_rel[r], b_src[r] + k0);
            }
        }
        CP_COMMIT();

#pragma unroll
        for (int ks = 0; ks < 2; ks++) {
            uint32_t af[4][4];
#pragma unroll
            for (int mt = 0; mt < 4; mt++)
                ldsm_x4(sA[buf] + a_off[mt][ks], af[mt][0], af[mt][1], af[mt][2], af[mt][3]);
            uint32_t bf[2][4];
#pragma unroll
            for (int ntp = 0; ntp < 2; ntp++)
                ldsm_x4(sB[buf] + b_off[ntp][ks], bf[ntp][0], bf[ntp][1], bf[ntp][2], bf[ntp][3]);
#pragma unroll
            for (int mt = 0; mt < 4; mt++)
#pragma unroll
                for (int nt = 0; nt < 4; nt++) {
                    const uint32_t* bp = &bf[nt >> 1][(nt & 1) * 2];
                    mma_tf32(c[mt][nt][0], c[mt][nt][1], c[mt][nt][2], c[mt][nt][3],
                             af[mt][0], af[mt][1], af[mt][2], af[mt][3], bp[0], bp[1]);
                }
        }

        CP_WAIT(1);
        __syncthreads();
        buf = (buf + 1 == GSTG) ? 0 : buf + 1;
        nxt = (nxt + 1 == GSTG) ? 0 : nxt + 1;
    }

    const int rql = lane >> 2;
    const int cpl = (lane & 3) * 2;
#pragma unroll
    for (int mt = 0; mt < 4; mt++) {
        int rg = row0 + warp_m * 64 + mt * 16 + rql;
#pragma unroll
        for (int nt = 0; nt < 4; nt++) {
            int cg = col0 + warp_n * 32 + nt * 8 + cpl;
            if (ROUND) {
                uint2 v0 = {f2tf32(c[mt][nt][0]), f2tf32(c[mt][nt][1])};
                uint2 v1 = {f2tf32(c[mt][nt][2]), f2tf32(c[mt][nt][3])};
                *(uint2*)(C + (size_t)rg * N + cg)       = v0;
                *(uint2*)(C + (size_t)(rg + 8) * N + cg) = v1;
            } else {
                float2 v0 = {c[mt][nt][0], c[mt][nt][1]};
                float2 v1 = {c[mt][nt][2], c[mt][nt][3]};
                *(float2*)(C + (size_t)rg * N + cg)       = v0;
                *(float2*)(C + (size_t)(rg + 8) * N + cg) = v1;
            }
        }
    }
}

// ---------------------------------------------------------------------------
// V transpose: g_vt[b][h][d][s] = qkv[b][s][2*D + h*64 + d]   (qkv pre-rounded)
// ---------------------------------------------------------------------------
__global__ __launch_bounds__(256)
void vtrans(const float* __restrict__ qkv, float* __restrict__ vt) {
    __shared__ float t[32][33];
    const int bh = blockIdx.z;
    const int b  = bh >> 4, h = bh & 15;
    const int s0 = blockIdx.x * 32;
    const int d0 = blockIdx.y * 32;
    const int txx = threadIdx.x, tyy = threadIdx.y;

#pragma unroll
    for (int i = tyy; i < 32; i += 8)
        t[i][txx] = qkv[((size_t)(b * S_LEN) + s0 + i) * D3 + 2 * D_MODEL + h * DH + d0 + txx];
    __syncthreads();
#pragma unroll
    for (int i = tyy; i < 32; i += 8)
        vt[((size_t)bh * DH + d0 + i) * S_LEN + s0 + txx] = t[txx][i];
}

// ---------------------------------------------------------------------------
// Tensor-core causal flash attention; K/V tiles via cp.async (pre-rounded).
// ---------------------------------------------------------------------------
#define AQ_SWZ(row, k) ((row) * 64 + ((((k) >> 2) ^ ((row) & 7)) << 2) + ((k) & 3))
#define ATT_SCALE 0.18033688f   /* 0.125 * log2(e) */

__global__ __launch_bounds__(256)
void attn_tc(const float* __restrict__ qkv, const float* __restrict__ vt,
             float* __restrict__ y) {
    extern __shared__ uint32_t smu[];
    uint32_t* Qs = smu;            // 128*64
    const uint32_t qs_base = (uint32_t)__cvta_generic_to_shared(Qs);
    const uint32_t ks_base = qs_base + 32768;
    const uint32_t vs_base = ks_base + 32768;

    const int tid  = threadIdx.x;
    const int lane = tid & 31;
    const int w    = tid >> 5;
    const int qi   = (S_LEN / 128 - 1) - blockIdx.x;
    const int h    = blockIdx.y;
    const int b    = blockIdx.z;
    const int q0   = qi * 128;

    const float* qb = qkv + (size_t)b * S_LEN * D3 + h * DH;
    const float* kb = qb + D_MODEL;
    const float* vb = vt + ((size_t)(b * N_HEADS + h)) * DH * S_LEN;

    int l_row[4], l_chk[4];
    uint32_t l_rel[4];
#pragma unroll
    for (int r = 0; r < 4; r++) {
        int idx = tid + 256 * r;
        l_row[r] = idx >> 4; l_chk[r] = idx & 15;
        l_rel[r] = (uint32_t)(AQ_SWZ(l_row[r], l_chk[r] * 4) * 4);
    }

    // issue K/V tile 0
#pragma unroll
    for (int r = 0; r < 4; r++) {
        cp16(ks_base + l_rel[r], kb + (size_t)l_row[r] * D3 + l_chk[r] * 4);
        cp16(vs_base + l_rel[r], vb + (size_t)l_row[r] * S_LEN + l_chk[r] * 4);
    }
    CP_COMMIT();

    // load Q (scale + round)
#pragma unroll
    for (int r = 0; r < 8; r++) {
        int idx = tid + 256 * r, row = idx >> 4, ch = idx & 15;
        float4 v = *(const float4*)(qb + (size_t)(q0 + row) * D3 + ch * 4);
        uint32_t* d = &Qs[AQ_SWZ(row, ch * 4)];
        d[0] = f2tf32(v.x * ATT_SCALE); d[1] = f2tf32(v.y * ATT_SCALE);
        d[2] = f2tf32(v.z * ATT_SCALE); d[3] = f2tf32(v.w * ATT_SCALE);
    }
    CP_WAIT(0);
    __syncthreads();

    // Q fragments (loop-invariant)
    const int mat = lane >> 3, rr = lane & 7;
    uint32_t qf[8][4];
    {
        int rowA = w * 16 + ((mat & 1) << 3) + rr;
        int rbase = rowA * 256;
        int rx = rowA & 7;
#pragma unroll
        for (int ks = 0; ks < 8; ks++) {
            int kc = ks * 2 + (mat >> 1);
            ldsm_x4(qs_base + rbase + ((kc ^ rx) << 4), qf[ks][0], qf[ks][1], qf[ks][2], qf[ks][3]);
        }
    }
    uint32_t browOff[4]; int brx[4];
#pragma unroll
    for (int ntp = 0; ntp < 4; ntp++) {
        int rowB = ntp * 16 + ((mat >> 1) << 3) + rr;
        browOff[ntp] = (uint32_t)(rowB * 256);
        brx[ntp] = rowB & 7;
    }
    const int kbit = mat & 1;

    float m_lo = -1e30f, m_hi = -1e30f, l_lo = 0.f, l_hi = 0.f;
    float co[8][4];
#pragma unroll
    for (int i = 0; i < 8; i++)
#pragma unroll
        for (int q = 0; q < 4; q++) co[i][q] = 0.f;

    const int rlo  = q0 + w * 16 + (lane >> 2);
    const int jsel = lane & 3;
    const int src0 = (lane & 28) | (jsel >> 1);

    const int njb = 2 * qi + 2;
    int buf = 0;

    for (int jb = 0; jb < njb; jb++) {
        if (jb + 1 < njb) {
            const int kn = (jb + 1) * 64;
            const uint32_t kd = ks_base + (buf ^ 1) * 16384;
            const uint32_t vd = vs_base + (buf ^ 1) * 16384;
#pragma unroll
            for (int r = 0; r < 4; r++) {
                cp16(kd + l_rel[r], kb + (size_t)(kn + l_row[r]) * D3 + l_chk[r] * 4);
                cp16(vd + l_rel[r], vb + (size_t)l_row[r] * S_LEN + kn + l_chk[r] * 4);
            }
        }
        CP_COMMIT();

        const uint32_t kbuf = ks_base + (uint32_t)(buf * 16384);
        const uint32_t vbuf = vs_base + (uint32_t)(buf * 16384);

        // ---- S = Q @ K^T ----
        float cs[8][4];
#pragma unroll
        for (int i = 0; i < 8; i++)
#pragma unroll
            for (int q = 0; q < 4; q++) cs[i][q] = 0.f;

#pragma unroll
        for (int ks = 0; ks < 8; ks++) {
            uint32_t bf[4][4];
            int kc = ks * 2 + kbit;
#pragma unroll
            for (int ntp = 0; ntp < 4; ntp++)
                ldsm_x4(kbuf + browOff[ntp] + (((kc ^ brx[ntp])) << 4),
                        bf[ntp][0], bf[ntp][1], bf[ntp][2], bf[ntp][3]);
#pragma unroll
            for (int nt = 0; nt < 8; nt++) {
                const uint32_t* bp = &bf[nt >> 1][(nt & 1) * 2];
                mma_tf32(cs[nt][0], cs[nt][1], cs[nt][2], cs[nt][3],
                         qf[ks][0], qf[ks][1], qf[ks][2], qf[ks][3], bp[0], bp[1]);
            }
        }

        if (jb * 64 >= q0) {
#pragma unroll
            for (int nt = 0; nt < 8; nt++) {
                int cb = jb * 64 + nt * 8 + 2 * jsel;
                if (cb     > rlo)     cs[nt][0] = -1e30f;
                if (cb + 1 > rlo)     cs[nt][1] = -1e30f;
                if (cb     > rlo + 8) cs[nt][2] = -1e30f;
                if (cb + 1 > rlo + 8) cs[nt][3] = -1e30f;
            }
        }

        // ---- online softmax (base-2) ----
        float ml = -1e30f, mh = -1e30f;
#pragma unroll
        for (int nt = 0; nt < 8; nt++) {
            ml = fmaxf(ml, fmaxf(cs[nt][0], cs[nt][1]));
            mh = fmaxf(mh, fmaxf(cs[nt][2], cs[nt][3]));
        }
        ml = fmaxf(ml, __shfl_xor_sync(0xffffffffu, ml, 1));
        ml = fmaxf(ml, __shfl_xor_sync(0xffffffffu, ml, 2));
        mh = fmaxf(mh, __shfl_xor_sync(0xffffffffu, mh, 1));
        mh = fmaxf(mh, __shfl_xor_sync(0xffffffffu, mh, 2));
        float Ml = fmaxf(m_lo, ml), Mh = fmaxf(m_hi, mh);
        float al = ex2f(m_lo - Ml), ah = ex2f(m_hi - Mh);
        m_lo = Ml; m_hi = Mh;

        float sl = 0.f, sh2 = 0.f;
#pragma unroll
        for (int nt = 0; nt < 8; nt++) {
            cs[nt][0] = ex2f(cs[nt][0] - Ml);
            cs[nt][1] = ex2f(cs[nt][1] - Ml);
            cs[nt][2] = ex2f(cs[nt][2] - Mh);
            cs[nt][3] = ex2f(cs[nt][3] - Mh);
            sl  += cs[nt][0] + cs[nt][1];
            sh2 += cs[nt][2] + cs[nt][3];
        }
        sl  += __shfl_xor_sync(0xffffffffu, sl, 1);
        sl  += __shfl_xor_sync(0xffffffffu, sl, 2);
        sh2 += __shfl_xor_sync(0xffffffffu, sh2, 1);
        sh2 += __shfl_xor_sync(0xffffffffu, sh2, 2);
        l_lo = l_lo * al + sl;
        l_hi = l_hi * ah + sh2;
#pragma unroll
        for (int i = 0; i < 8; i++) {
            co[i][0] *= al; co[i][1] *= al; co[i][2] *= ah; co[i][3] *= ah;
        }

        // ---- O += P @ V ----
#pragma unroll
        for (int kt = 0; kt < 8; kt++) {
            float v00 = __shfl_sync(0xffffffffu, cs[kt][0], src0);
            float v01 = __shfl_sync(0xffffffffu, cs[kt][1], src0);
            float v20 = __shfl_sync(0xffffffffu, cs[kt][0], src0 + 2);
            float v21 = __shfl_sync(0xffffffffu, cs[kt][1], src0 + 2);
            float v10 = __shfl_sync(0xffffffffu, cs[kt][2], src0);
            float v11 = __shfl_sync(0xffffffffu, cs[kt][3], src0);
            float v30 = __shfl_sync(0xffffffffu, cs[kt][2], src0 + 2);
            float v31 = __shfl_sync(0xffffffffu, cs[kt][3], src0 + 2);
            uint32_t pa0 = f2tf32((jsel & 1) ? v01 : v00);
            uint32_t pa1 = f2tf32((jsel & 1) ? v11 : v10);
            uint32_t pa2 = f2tf32((jsel & 1) ? v21 : v20);
            uint32_t pa3 = f2tf32((jsel & 1) ? v31 : v30);

            uint32_t bf[4];
            int kc = kt * 2 + kbit;
#pragma unroll
            for (int ntp = 0; ntp < 4; ntp++) {
                ldsm_x4(vbuf + browOff[ntp] + (((kc ^ brx[ntp])) << 4),
                        bf[0], bf[1], bf[2], bf[3]);
                mma_tf32(co[2 * ntp][0], co[2 * ntp][1], co[2 * ntp][2], co[2 * ntp][3],
                         pa0, pa1, pa2, pa3, bf[0], bf[1]);
                mma_tf32(co[2 * ntp + 1][0], co[2 * ntp + 1][1], co[2 * ntp + 1][2], co[2 * ntp + 1][3],
                         pa0, pa1, pa2, pa3, bf[2], bf[3]);
            }
        }

        CP_WAIT(0);
        __syncthreads();
        buf ^= 1;
    }

    // epilogue: y rounded to tf32 bits (feeds GEMM2 directly)
    const float il = 1.0f / l_lo, ih = 1.0f / l_hi;
    float* yb = y + ((size_t)b * S_LEN + q0 + w * 16 + (lane >> 2)) * D_MODEL + h * DH + 2 * jsel;
#pragma unroll
    for (int nt = 0; nt < 8; nt++) {
        uint2 v0 = {f2tf32(co[nt][0] * il), f2tf32(co[nt][1] * il)};
        uint2 v1 = {f2tf32(co[nt][2] * ih), f2tf32(co[nt][3] * ih)};
        *(uint2*)(yb + nt * 8)                       = v0;
        *(uint2*)(yb + nt * 8 + 8 * (size_t)D_MODEL) = v1;
    }
}

// ---------------------------------------------------------------------------
extern "C" void kernel_launch(void* const* d_in, const int* in_sizes, int n_in,
                              void* d_out, int out_size) {
    const float* x      = (const float*)d_in[0];
    const float* w_attn = (const float*)d_in[1];
    const float* w_proj = (const float*)d_in[2];
    float* out = (float*)d_out;

    float *qkv, *yb, *vt, *xc, *wac, *wpc;
    cudaGetSymbolAddress((void**)&qkv, g_qkv);
    cudaGetSymbolAddress((void**)&yb, g_y);
    cudaGetSymbolAddress((void**)&vt, g_vt);
    cudaGetSymbolAddress((void**)&xc, g_xc);
    cudaGetSymbolAddress((void**)&wac, g_wac);
    cudaGetSymbolAddress((void**)&wpc, g_wpc);

    const int gemm_smem = GSTG * 16384;  // 49152
    cudaFuncSetAttribute(gemm_tf32_cp<true>,  cudaFuncAttributeMaxDynamicSharedMemorySize, gemm_smem);
    cudaFuncSetAttribute(gemm_tf32_cp<false>, cudaFuncAttributeMaxDynamicSharedMemorySize, gemm_smem);
    const int attn_smem = 98304;
    cudaFuncSetAttribute(attn_tc, cudaFuncAttributeMaxDynamicSharedMemorySize, attn_smem);

    // pre-round operands to tf32
    round_tf32<<<(M_ROWS * D_MODEL / 4 + 255) / 256, 256>>>(x, xc, M_ROWS * D_MODEL / 4);
    round_tf32<<<(D3 * D_MODEL / 4 + 255) / 256, 256>>>(w_attn, wac, D3 * D_MODEL / 4);
    round_tf32<<<(D_MODEL * D_MODEL / 4 + 255) / 256, 256>>>(w_proj, wpc, D_MODEL * D_MODEL / 4);

    // GEMM1: qkv = x @ w_attn^T (output rounded to tf32)
    dim3 g1(D3 / TBN, M_ROWS / TBM);
    gemm_tf32_cp<true><<<g1, 256, gemm_smem>>>(xc, wac, qkv, M_ROWS, D3, D_MODEL);

    // V transpose
    dim3 gt(S_LEN / 32, DH / 32, BATCH * N_HEADS);
    vtrans<<<gt, dim3(32, 8)>>>(qkv, vt);

    // attention (y rounded to tf32)
    dim3 ga(S_LEN / 128, N_HEADS, BATCH);
    attn_tc<<<ga, 256, attn_smem>>>(qkv, vt, yb);

    // GEMM2: out = y @ w_proj^T (raw fp32 out)
    dim3 g2(D_MODEL / TBN, M_ROWS / TBM);
    gemm_tf32_cp<false><<<g2, 256, gemm_smem>>>(yb, wpc, out, M_ROWS, D_MODEL, D_MODEL);
}

// round 6
// speedup vs baseline: 11.3253x; 1.8799x over previous
#include <cuda_runtime.h>
#include <cuda_fp16.h>
#include <cstdint>
#include <cstddef>

// ---------------------------------------------------------------------------
// CausalSelfAttention: out = proj( causal_attn( x @ Wqkv^T ) )
// All matmuls on fp16 mma.sync m16n8k16 (fp32 accum). Operands pre-rounded to
// fp16 once; V consumed via ldmatrix.trans (no explicit transpose kernel).
// ---------------------------------------------------------------------------

#define BATCH   4
#define S_LEN   2048
#define D_MODEL 1024
#define D3      3072
#define N_HEADS 16
#define DH      64
#define M_ROWS  (BATCH * S_LEN)   // 8192

__device__ __half g_qkv[(size_t)M_ROWS * D3];       // GEMM1 out (fp16)
__device__ __half g_y[(size_t)M_ROWS * D_MODEL];    // attn out (fp16)
__device__ __half g_xc[(size_t)M_ROWS * D_MODEL];   // x -> fp16
__device__ __half g_wac[(size_t)D3 * D_MODEL];      // w_attn -> fp16
__device__ __half g_wpc[(size_t)D_MODEL * D_MODEL]; // w_proj -> fp16

// ---- helpers ----------------------------------------------------------------
__device__ __forceinline__ uint32_t pack_h2(float a, float b) {
    __half2 h = __floats2half2_rn(a, b);
    return *(uint32_t*)&h;
}
__device__ __forceinline__ float ex2f(float x) {
    float r;
    asm("ex2.approx.ftz.f32 %0, %1;" : "=f"(r) : "f"(x));
    return r;
}
__device__ __forceinline__ void ldsm_x4(uint32_t addr, uint32_t& r0, uint32_t& r1,
                                        uint32_t& r2, uint32_t& r3) {
    asm volatile("ldmatrix.sync.aligned.m8n8.x4.shared.b16 {%0,%1,%2,%3}, [%4];"
                 : "=r"(r0), "=r"(r1), "=r"(r2), "=r"(r3) : "r"(addr));
}
__device__ __forceinline__ void ldsm_x4t(uint32_t addr, uint32_t& r0, uint32_t& r1,
                                         uint32_t& r2, uint32_t& r3) {
    asm volatile("ldmatrix.sync.aligned.m8n8.x4.trans.shared.b16 {%0,%1,%2,%3}, [%4];"
                 : "=r"(r0), "=r"(r1), "=r"(r2), "=r"(r3) : "r"(addr));
}
__device__ __forceinline__ void mma_f16(float& c0, float& c1, float& c2, float& c3,
                                        uint32_t a0, uint32_t a1, uint32_t a2, uint32_t a3,
                                        uint32_t b0, uint32_t b1) {
    asm volatile("mma.sync.aligned.m16n8k16.row.col.f32.f16.f16.f32 "
                 "{%0,%1,%2,%3}, {%4,%5,%6,%7}, {%8,%9}, {%0,%1,%2,%3};"
                 : "+f"(c0), "+f"(c1), "+f"(c2), "+f"(c3)
                 : "r"(a0), "r"(a1), "r"(a2), "r"(a3), "r"(b0), "r"(b1));
}
__device__ __forceinline__ void cp16(uint32_t dst, const void* src) {
    asm volatile("cp.async.cg.shared.global [%0], [%1], 16;" :: "r"(dst), "l"(src));
}
#define CP_COMMIT() asm volatile("cp.async.commit_group;")
#define CP_WAIT(n)  asm volatile("cp.async.wait_group %0;" :: "n"(n))

__device__ __forceinline__ uint32_t smem_u32(const void* p) {
    return (uint32_t)__cvta_generic_to_shared(p);
}

// ---------------------------------------------------------------------------
// Pre-round fp32 -> fp16
// ---------------------------------------------------------------------------
__global__ void round_f16(const float* __restrict__ in, __half* __restrict__ out, int n4) {
    int i = blockIdx.x * blockDim.x + threadIdx.x;
    if (i < n4) {
        float4 v = ((const float4*)in)[i];
        uint2 r = {pack_h2(v.x, v.y), pack_h2(v.z, v.w)};
        ((uint2*)out)[i] = r;
    }
}

// ---------------------------------------------------------------------------
// fp16 GEMM (NT), cp.async 3-stage: C[M,N] = A[M,K] @ B[N,K]^T
// Block 128x128x(K32 halfs), 8 warps (2x4), warp tile 64x32.
// SMEM rows = 32 halfs = 64B, 4x16B chunks, swizzle chunk^((row>>1)&3).
// ---------------------------------------------------------------------------
#define TBM 128
#define TBN 128
#define TBKH 32          // K per stage, in halfs
#define GSTG 3
#define G_STAGE_BYTES 16384        // 8KB A + 8KB B
#define GEMM_SMEM (GSTG * G_STAGE_BYTES)

template <bool HALF_OUT>
__global__ __launch_bounds__(256)
void gemm_f16(const __half* __restrict__ A, const __half* __restrict__ B,
              void* __restrict__ Cv, int M, int N, int K) {
    extern __shared__ uint32_t sh[];

    const int tid    = threadIdx.x;
    const int lane   = tid & 31;
    const int warp   = tid >> 5;
    const int warp_m = warp >> 2;
    const int warp_n = warp & 3;
    const int row0   = blockIdx.y * TBM;
    const int col0   = blockIdx.x * TBN;

    const __half* Ab = A + (size_t)row0 * K;
    const __half* Bb = B + (size_t)col0 * K;

    const uint32_t base = smem_u32(sh);
    uint32_t sA[GSTG], sB[GSTG];
#pragma unroll
    for (int s = 0; s < GSTG; s++) { sA[s] = base + s * G_STAGE_BYTES; sB[s] = sA[s] + 8192; }

    // per-thread cp.async mapping: 2 chunks A + 2 chunks B (16B each)
    const __half* a_src[2];
    const __half* b_src[2];
    uint32_t a_rel[2], b_rel[2];
#pragma unroll
    for (int r = 0; r < 2; r++) {
        int idx = tid + 256 * r, row = idx >> 2, c = idx & 3;
        a_src[r] = Ab + (size_t)row * K + c * 8;
        b_src[r] = Bb + (size_t)row * K + c * 8;
        uint32_t rel = (uint32_t)(row * 64 + ((c ^ ((row >> 1) & 3)) << 4));
        a_rel[r] = rel; b_rel[r] = rel;
    }

    // ldsm byte offsets within a stage
    uint32_t a_off[4][2], b_off[2][2];
    {
        int mat = lane >> 3, r = lane & 7;
#pragma unroll
        for (int mt = 0; mt < 4; mt++)
#pragma unroll
            for (int ks = 0; ks < 2; ks++) {
                int row = warp_m * 64 + mt * 16 + ((mat & 1) << 3) + r;
                int ch  = ks * 2 + (mat >> 1);
                a_off[mt][ks] = (uint32_t)(row * 64 + ((ch ^ ((row >> 1) & 3)) << 4));
            }
#pragma unroll
        for (int ntp = 0; ntp < 2; ntp++)
#pragma unroll
            for (int ks = 0; ks < 2; ks++) {
                int row = warp_n * 32 + ntp * 16 + ((mat >> 1) << 3) + r;
                int ch  = ks * 2 + (mat & 1);
                b_off[ntp][ks] = (uint32_t)(row * 64 + ((ch ^ ((row >> 1) & 3)) << 4));
            }
    }

    float c[4][4][4];
#pragma unroll
    for (int i = 0; i < 4; i++)
#pragma unroll
        for (int j = 0; j < 4; j++)
#pragma unroll
            for (int q = 0; q < 4; q++) c[i][j][q] = 0.f;

    const int NIT = K / TBKH;   // 32

    // prologue: stages 0,1
#pragma unroll
    for (int s = 0; s < 2; s++) {
#pragma unroll
        for (int r = 0; r < 2; r++) {
            cp16(sA[s] + a_rel[r], a_src[r] + s * TBKH);
            cp16(sB[s] + b_rel[r], b_src[r] + s * TBKH);
        }
        CP_COMMIT();
    }
    CP_WAIT(1);
    __syncthreads();

    int buf = 0, nxt = 2;
    for (int it = 0; it < NIT; it++) {
        if (it + 2 < NIT) {
            const int k0 = (it + 2) * TBKH;
#pragma unroll
            for (int r = 0; r < 2; r++) {
                cp16(sA[nxt] + a_rel[r], a_src[r] + k0);
                cp16(sB[nxt] + b_rel[r], b_src[r] + k0);
            }
        }
        CP_COMMIT();

#pragma unroll
        for (int ks = 0; ks < 2; ks++) {
            uint32_t af[4][4];
#pragma unroll
            for (int mt = 0; mt < 4; mt++)
                ldsm_x4(sA[buf] + a_off[mt][ks], af[mt][0], af[mt][1], af[mt][2], af[mt][3]);
            uint32_t bf[2][4];
#pragma unroll
            for (int ntp = 0; ntp < 2; ntp++)
                ldsm_x4(sB[buf] + b_off[ntp][ks], bf[ntp][0], bf[ntp][1], bf[ntp][2], bf[ntp][3]);
#pragma unroll
            for (int mt = 0; mt < 4; mt++)
#pragma unroll
                for (int nt = 0; nt < 4; nt++) {
                    const uint32_t* bp = &bf[nt >> 1][(nt & 1) * 2];
                    mma_f16(c[mt][nt][0], c[mt][nt][1], c[mt][nt][2], c[mt][nt][3],
                            af[mt][0], af[mt][1], af[mt][2], af[mt][3], bp[0], bp[1]);
                }
        }

        CP_WAIT(1);
        __syncthreads();
        buf = (buf + 1 == GSTG) ? 0 : buf + 1;
        nxt = (nxt + 1 == GSTG) ? 0 : nxt + 1;
    }

    const int rql = lane >> 2;
    const int cpl = (lane & 3) * 2;
#pragma unroll
    for (int mt = 0; mt < 4; mt++) {
        int rg = row0 + warp_m * 64 + mt * 16 + rql;
#pragma unroll
        for (int nt = 0; nt < 4; nt++) {
            int cg = col0 + warp_n * 32 + nt * 8 + cpl;
            if (HALF_OUT) {
                __half* C = (__half*)Cv;
                *(uint32_t*)(C + (size_t)rg * N + cg)       = pack_h2(c[mt][nt][0], c[mt][nt][1]);
                *(uint32_t*)(C + (size_t)(rg + 8) * N + cg) = pack_h2(c[mt][nt][2], c[mt][nt][3]);
            } else {
                float* C = (float*)Cv;
                float2 v0 = {c[mt][nt][0], c[mt][nt][1]};
                float2 v1 = {c[mt][nt][2], c[mt][nt][3]};
                *(float2*)(C + (size_t)rg * N + cg)       = v0;
                *(float2*)(C + (size_t)(rg + 8) * N + cg) = v1;
            }
        }
    }
}

// ---------------------------------------------------------------------------
// fp16 causal flash attention. Block = 128 q-rows, 64 kv/iter, 8 warps.
// Q/K tiles [row][d] 64 halfs = 128B rows; V tile [kv][d] consumed via
// ldmatrix.trans. SMEM swizzle: 16B chunk ^ (row & 7).
// ---------------------------------------------------------------------------
#define ATT_SCALE 0.18033688f   /* 0.125 * log2(e) */
#define ATT_SMEM  49152         /* Q 16K + K 2x8K + V 2x8K */

__global__ __launch_bounds__(256)
void attn_f16(const __half* __restrict__ qkv, __half* __restrict__ y) {
    extern __shared__ uint32_t smu[];
    char* smc = (char*)smu;
    const uint32_t qs_base = smem_u32(smu);
    const uint32_t ks_base = qs_base + 16384;
    const uint32_t vs_base = ks_base + 16384;

    const int tid  = threadIdx.x;
    const int lane = tid & 31;
    const int w    = tid >> 5;
    const int qi   = (S_LEN / 128 - 1) - blockIdx.x;   // heavy tiles first
    const int h    = blockIdx.y;
    const int b    = blockIdx.z;
    const int q0   = qi * 128;

    const __half* qb = qkv + (size_t)b * S_LEN * D3 + h * DH;
    const __half* kb = qb + D_MODEL;
    const __half* vb = qb + 2 * D_MODEL;

    // K/V cp.async mapping: 64 rows x 8 chunks = 512; 2 per thread
    int l_row[2], l_chk[2];
    uint32_t l_rel[2];
#pragma unroll
    for (int r = 0; r < 2; r++) {
        int idx = tid + 256 * r;
        l_row[r] = idx >> 3; l_chk[r] = idx & 7;
        l_rel[r] = (uint32_t)(l_row[r] * 128 + ((l_chk[r] ^ (l_row[r] & 7)) << 4));
    }

    // issue K/V tile 0
#pragma unroll
    for (int r = 0; r < 2; r++) {
        cp16(ks_base + l_rel[r], kb + (size_t)l_row[r] * D3 + l_chk[r] * 8);
        cp16(vs_base + l_rel[r], vb + (size_t)l_row[r] * D3 + l_chk[r] * 8);
    }
    CP_COMMIT();

    // load Q (scale in fp32, repack fp16): 128 rows x 8 chunks = 1024; 4/thread
#pragma unroll
    for (int r = 0; r < 4; r++) {
        int idx = tid + 256 * r, row = idx >> 3, ch = idx & 7;
        uint4 raw = *(const uint4*)(qb + (size_t)(q0 + row) * D3 + ch * 8);
        uint32_t* rp = (uint32_t*)&raw;
        uint4 outv;
        uint32_t* op = (uint32_t*)&outv;
#pragma unroll
        for (int j = 0; j < 4; j++) {
            __half2 hv = *(__half2*)&rp[j];
            float2 f = __half22float2(hv);
            op[j] = pack_h2(f.x * ATT_SCALE, f.y * ATT_SCALE);
        }
        *(uint4*)(smc + row * 128 + ((ch ^ (row & 7)) << 4)) = outv;
    }
    CP_WAIT(0);
    __syncthreads();

    // Q fragments (loop-invariant): qf[ks 0..3][4]
    const int mat = lane >> 3, rr = lane & 7;
    uint32_t qf[4][4];
    {
        int rowA = w * 16 + ((mat & 1) << 3) + rr;
        int rbase = rowA * 128;
        int rx = rowA & 7;
#pragma unroll
        for (int ks = 0; ks < 4; ks++) {
            int ch = ks * 2 + (mat >> 1);
            ldsm_x4(qs_base + rbase + ((ch ^ rx) << 4), qf[ks][0], qf[ks][1], qf[ks][2], qf[ks][3]);
        }
    }
    // K-side ldsm constants: row = kv, per (ntp, ks)
    uint32_t krowOff[4]; int krx[4];
#pragma unroll
    for (int ntp = 0; ntp < 4; ntp++) {
        int rowB = ntp * 16 + ((mat >> 1) << 3) + rr;
        krowOff[ntp] = (uint32_t)(rowB * 128);
        krx[ntp] = rowB & 7;
    }
    const int kbit = mat & 1;
    // V-side (trans) ldsm constants: row = kv = 16*kt + ((mat&1)<<3) + rr
    uint32_t vrowOff[4]; int vrx[4];
#pragma unroll
    for (int kt = 0; kt < 4; kt++) {
        int rowV = kt * 16 + ((mat & 1) << 3) + rr;
        vrowOff[kt] = (uint32_t)(rowV * 128);
        vrx[kt] = rowV & 7;
    }
    const int vbit = mat >> 1;

    float m_lo = -1e30f, m_hi = -1e30f, l_lo = 0.f, l_hi = 0.f;
    float co[8][4];
#pragma unroll
    for (int i = 0; i < 8; i++)
#pragma unroll
        for (int q = 0; q < 4; q++) co[i][q] = 0.f;

    const int rlo  = q0 + w * 16 + (lane >> 2);
    const int jsel = lane & 3;

    const int njb = 2 * qi + 2;
    int buf = 0;

    for (int jb = 0; jb < njb; jb++) {
        if (jb + 1 < njb) {
            const int kn = (jb + 1) * 64;
            const uint32_t kd = ks_base + (buf ^ 1) * 8192;
            const uint32_t vd = vs_base + (buf ^ 1) * 8192;
#pragma unroll
            for (int r = 0; r < 2; r++) {
                cp16(kd + l_rel[r], kb + (size_t)(kn + l_row[r]) * D3 + l_chk[r] * 8);
                cp16(vd + l_rel[r], vb + (size_t)(kn + l_row[r]) * D3 + l_chk[r] * 8);
            }
        }
        CP_COMMIT();

        const uint32_t kbuf = ks_base + (uint32_t)(buf * 8192);
        const uint32_t vbuf = vs_base + (uint32_t)(buf * 8192);

        // ---- S = Q @ K^T ----
        float cs[8][4];
#pragma unroll
        for (int i = 0; i < 8; i++)
#pragma unroll
            for (int q = 0; q < 4; q++) cs[i][q] = 0.f;

#pragma unroll
        for (int ks = 0; ks < 4; ks++) {
            uint32_t bf[4][4];
            int ch = ks * 2 + kbit;
#pragma unroll
            for (int ntp = 0; ntp < 4; ntp++)
                ldsm_x4(kbuf + krowOff[ntp] + ((ch ^ krx[ntp]) << 4),
                        bf[ntp][0], bf[ntp][1], bf[ntp][2], bf[ntp][3]);
#pragma unroll
            for (int nt = 0; nt < 8; nt++) {
                const uint32_t* bp = &bf[nt >> 1][(nt & 1) * 2];
                mma_f16(cs[nt][0], cs[nt][1], cs[nt][2], cs[nt][3],
                        qf[ks][0], qf[ks][1], qf[ks][2], qf[ks][3], bp[0], bp[1]);
            }
        }

        // ---- causal mask ----
        if (jb * 64 >= q0) {
#pragma unroll
            for (int nt = 0; nt < 8; nt++) {
                int cb = jb * 64 + nt * 8 + 2 * jsel;
                if (cb     > rlo)     cs[nt][0] = -1e30f;
                if (cb + 1 > rlo)     cs[nt][1] = -1e30f;
                if (cb     > rlo + 8) cs[nt][2] = -1e30f;
                if (cb + 1 > rlo + 8) cs[nt][3] = -1e30f;
            }
        }

        // ---- online softmax (base-2) ----
        float ml = -1e30f, mh = -1e30f;
#pragma unroll
        for (int nt = 0; nt < 8; nt++) {
            ml = fmaxf(ml, fmaxf(cs[nt][0], cs[nt][1]));
            mh = fmaxf(mh, fmaxf(cs[nt][2], cs[nt][3]));
        }
        ml = fmaxf(ml, __shfl_xor_sync(0xffffffffu, ml, 1));
        ml = fmaxf(ml, __shfl_xor_sync(0xffffffffu, ml, 2));
        mh = fmaxf(mh, __shfl_xor_sync(0xffffffffu, mh, 1));
        mh = fmaxf(mh, __shfl_xor_sync(0xffffffffu, mh, 2));
        float Ml = fmaxf(m_lo, ml), Mh = fmaxf(m_hi, mh);
        float al = ex2f(m_lo - Ml), ah = ex2f(m_hi - Mh);
        m_lo = Ml; m_hi = Mh;

        float sl = 0.f, sh2 = 0.f;
#pragma unroll
        for (int nt = 0; nt < 8; nt++) {
            cs[nt][0] = ex2f(cs[nt][0] - Ml);
            cs[nt][1] = ex2f(cs[nt][1] - Ml);
            cs[nt][2] = ex2f(cs[nt][2] - Mh);
            cs[nt][3] = ex2f(cs[nt][3] - Mh);
            sl  += cs[nt][0] + cs[nt][1];
            sh2 += cs[nt][2] + cs[nt][3];
        }
        sl  += __shfl_xor_sync(0xffffffffu, sl, 1);
        sl  += __shfl_xor_sync(0xffffffffu, sl, 2);
        sh2 += __shfl_xor_sync(0xffffffffu, sh2, 1);
        sh2 += __shfl_xor_sync(0xffffffffu, sh2, 2);
        l_lo = l_lo * al + sl;
        l_hi = l_hi * ah + sh2;
#pragma unroll
        for (int i = 0; i < 8; i++) {
            co[i][0] *= al; co[i][1] *= al; co[i][2] *= ah; co[i][3] *= ah;
        }

        // ---- O += P @ V : P packs directly into A-fragments (no shuffles) ----
#pragma unroll
        for (int kt = 0; kt < 4; kt++) {
            uint32_t pa0 = pack_h2(cs[2 * kt][0],     cs[2 * kt][1]);
            uint32_t pa1 = pack_h2(cs[2 * kt][2],     cs[2 * kt][3]);
            uint32_t pa2 = pack_h2(cs[2 * kt + 1][0], cs[2 * kt + 1][1]);
            uint32_t pa3 = pack_h2(cs[2 * kt + 1][2], cs[2 * kt + 1][3]);

#pragma unroll
            for (int ntp = 0; ntp < 4; ntp++) {
                uint32_t bf0, bf1, bf2, bf3;
                int ch = ntp * 2 + vbit;
                ldsm_x4t(vbuf + vrowOff[kt] + ((ch ^ vrx[kt]) << 4), bf0, bf1, bf2, bf3);
                mma_f16(co[2 * ntp][0], co[2 * ntp][1], co[2 * ntp][2], co[2 * ntp][3],
                        pa0, pa1, pa2, pa3, bf0, bf1);
                mma_f16(co[2 * ntp + 1][0], co[2 * ntp + 1][1], co[2 * ntp + 1][2], co[2 * ntp + 1][3],
                        pa0, pa1, pa2, pa3, bf2, bf3);
            }
        }

        CP_WAIT(0);
        __syncthreads();
        buf ^= 1;
    }

    // ---- epilogue: y (fp16) = O / l ----
    const float il = 1.0f / l_lo, ih = 1.0f / l_hi;
    __half* yb = y + ((size_t)b * S_LEN + q0 + w * 16 + (lane >> 2)) * D_MODEL + h * DH + 2 * jsel;
#pragma unroll
    for (int nt = 0; nt < 8; nt++) {
        *(uint32_t*)(yb + nt * 8)                       = pack_h2(co[nt][0] * il, co[nt][1] * il);
        *(uint32_t*)(yb + nt * 8 + 8 * (size_t)D_MODEL) = pack_h2(co[nt][2] * ih, co[nt][3] * ih);
    }
}

// ---------------------------------------------------------------------------
extern "C" void kernel_launch(void* const* d_in, const int* in_sizes, int n_in,
                              void* d_out, int out_size) {
    const float* x      = (const float*)d_in[0];
    const float* w_attn = (const float*)d_in[1];
    const float* w_proj = (const float*)d_in[2];
    float* out = (float*)d_out;

    __half *qkv, *yb, *xc, *wac, *wpc;
    cudaGetSymbolAddress((void**)&qkv, g_qkv);
    cudaGetSymbolAddress((void**)&yb, g_y);
    cudaGetSymbolAddress((void**)&xc, g_xc);
    cudaGetSymbolAddress((void**)&wac, g_wac);
    cudaGetSymbolAddress((void**)&wpc, g_wpc);

    cudaFuncSetAttribute(gemm_f16<true>,  cudaFuncAttributeMaxDynamicSharedMemorySize, GEMM_SMEM);
    cudaFuncSetAttribute(gemm_f16<false>, cudaFuncAttributeMaxDynamicSharedMemorySize, GEMM_SMEM);
    cudaFuncSetAttribute(attn_f16, cudaFuncAttributeMaxDynamicSharedMemorySize, ATT_SMEM);

    // pre-round operands to fp16
    round_f16<<<(M_ROWS * D_MODEL / 4 + 255) / 256, 256>>>(x, xc, M_ROWS * D_MODEL / 4);
    round_f16<<<(D3 * D_MODEL / 4 + 255) / 256, 256>>>(w_attn, wac, D3 * D_MODEL / 4);
    round_f16<<<(D_MODEL * D_MODEL / 4 + 255) / 256, 256>>>(w_proj, wpc, D_MODEL * D_MODEL / 4);

    // GEMM1: qkv = x @ w_attn^T   (fp16 out)
    dim3 g1(D3 / TBN, M_ROWS / TBM);
    gemm_f16<true><<<g1, 256, GEMM_SMEM>>>(xc, wac, qkv, M_ROWS, D3, D_MODEL);

    // fused causal attention -> y (fp16)
    dim3 ga(S_LEN / 128, N_HEADS, BATCH);
    attn_f16<<<ga, 256, ATT_SMEM>>>(qkv, yb);

    // GEMM2: out = y @ w_proj^T   (fp32 out)
    dim3 g2(D_MODEL / TBN, M_ROWS / TBM);
    gemm_f16<false><<<g2, 256, GEMM_SMEM>>>(yb, wpc, out, M_ROWS, D_MODEL, D_MODEL);
}

// round 7
// speedup vs baseline: 11.3474x; 1.0020x over previous
#include <cuda_runtime.h>
#include <cuda_fp16.h>
#include <cstdint>
#include <cstddef>

// ---------------------------------------------------------------------------
// CausalSelfAttention: out = proj( causal_attn( x @ Wqkv^T ) )
// fp16 mma.sync m16n8k16 (fp32 accum); 2 CTAs/SM; 4-stage cp.async GEMM ring.
// ---------------------------------------------------------------------------

#define BATCH   4
#define S_LEN   2048
#define D_MODEL 1024
#define D3      3072
#define N_HEADS 16
#define DH      64
#define M_ROWS  (BATCH * S_LEN)   // 8192

__device__ __half g_qkv[(size_t)M_ROWS * D3];
__device__ __half g_y[(size_t)M_ROWS * D_MODEL];
__device__ __half g_xc[(size_t)M_ROWS * D_MODEL];
__device__ __half g_wac[(size_t)D3 * D_MODEL];
__device__ __half g_wpc[(size_t)D_MODEL * D_MODEL];

// ---- helpers ----------------------------------------------------------------
__device__ __forceinline__ uint32_t pack_h2(float a, float b) {
    __half2 h = __floats2half2_rn(a, b);
    return *(uint32_t*)&h;
}
__device__ __forceinline__ float ex2f(float x) {
    float r;
    asm("ex2.approx.ftz.f32 %0, %1;" : "=f"(r) : "f"(x));
    return r;
}
__device__ __forceinline__ void ldsm_x4(uint32_t addr, uint32_t& r0, uint32_t& r1,
                                        uint32_t& r2, uint32_t& r3) {
    asm volatile("ldmatrix.sync.aligned.m8n8.x4.shared.b16 {%0,%1,%2,%3}, [%4];"
                 : "=r"(r0), "=r"(r1), "=r"(r2), "=r"(r3) : "r"(addr));
}
__device__ __forceinline__ void ldsm_x4t(uint32_t addr, uint32_t& r0, uint32_t& r1,
                                         uint32_t& r2, uint32_t& r3) {
    asm volatile("ldmatrix.sync.aligned.m8n8.x4.trans.shared.b16 {%0,%1,%2,%3}, [%4];"
                 : "=r"(r0), "=r"(r1), "=r"(r2), "=r"(r3) : "r"(addr));
}
__device__ __forceinline__ void mma_f16(float& c0, float& c1, float& c2, float& c3,
                                        uint32_t a0, uint32_t a1, uint32_t a2, uint32_t a3,
                                        uint32_t b0, uint32_t b1) {
    asm volatile("mma.sync.aligned.m16n8k16.row.col.f32.f16.f16.f32 "
                 "{%0,%1,%2,%3}, {%4,%5,%6,%7}, {%8,%9}, {%0,%1,%2,%3};"
                 : "+f"(c0), "+f"(c1), "+f"(c2), "+f"(c3)
                 : "r"(a0), "r"(a1), "r"(a2), "r"(a3), "r"(b0), "r"(b1));
}
__device__ __forceinline__ void cp16(uint32_t dst, const void* src) {
    asm volatile("cp.async.cg.shared.global [%0], [%1], 16;" :: "r"(dst), "l"(src));
}
#define CP_COMMIT() asm volatile("cp.async.commit_group;")
#define CP_WAIT(n)  asm volatile("cp.async.wait_group %0;" :: "n"(n))

__device__ __forceinline__ uint32_t smem_u32(const void* p) {
    return (uint32_t)__cvta_generic_to_shared(p);
}

// ---------------------------------------------------------------------------
// Pre-round fp32 -> fp16
// ---------------------------------------------------------------------------
__global__ void round_f16(const float* __restrict__ in, __half* __restrict__ out, int n4) {
    int i = blockIdx.x * blockDim.x + threadIdx.x;
    if (i < n4) {
        float4 v = ((const float4*)in)[i];
        uint2 r = {pack_h2(v.x, v.y), pack_h2(v.z, v.w)};
        ((uint2*)out)[i] = r;
    }
}

// ---------------------------------------------------------------------------
// fp16 GEMM (NT), cp.async 4-stage (prefetch depth 3):
// C[M,N] = A[M,K] @ B[N,K]^T. Block 128x128x(32 halfs), 8 warps, warp 64x32.
// ---------------------------------------------------------------------------
#define TBM 128
#define TBN 128
#define TBKH 32
#define GSTG 4
#define G_STAGE_BYTES 16384
#define GEMM_SMEM (GSTG * G_STAGE_BYTES)   // 65536

template <bool HALF_OUT>
__global__ __launch_bounds__(256, 2)
void gemm_f16(const __half* __restrict__ A, const __half* __restrict__ B,
              void* __restrict__ Cv, int M, int N, int K) {
    extern __shared__ uint32_t sh[];

    const int tid    = threadIdx.x;
    const int lane   = tid & 31;
    const int warp   = tid >> 5;
    const int warp_m = warp >> 2;
    const int warp_n = warp & 3;
    const int row0   = blockIdx.y * TBM;
    const int col0   = blockIdx.x * TBN;

    const __half* Ab = A + (size_t)row0 * K;
    const __half* Bb = B + (size_t)col0 * K;

    const uint32_t base = smem_u32(sh);
    uint32_t sA[GSTG], sB[GSTG];
#pragma unroll
    for (int s = 0; s < GSTG; s++) { sA[s] = base + s * G_STAGE_BYTES; sB[s] = sA[s] + 8192; }

    const __half* a_src[2];
    const __half* b_src[2];
    uint32_t a_rel[2];
#pragma unroll
    for (int r = 0; r < 2; r++) {
        int idx = tid + 256 * r, row = idx >> 2, c = idx & 3;
        a_src[r] = Ab + (size_t)row * K + c * 8;
        b_src[r] = Bb + (size_t)row * K + c * 8;
        a_rel[r] = (uint32_t)(row * 64 + ((c ^ ((row >> 1) & 3)) << 4));
    }

    uint32_t a_off[4][2], b_off[2][2];
    {
        int mat = lane >> 3, r = lane & 7;
#pragma unroll
        for (int mt = 0; mt < 4; mt++)
#pragma unroll
            for (int ks = 0; ks < 2; ks++) {
                int row = warp_m * 64 + mt * 16 + ((mat & 1) << 3) + r;
                int ch  = ks * 2 + (mat >> 1);
                a_off[mt][ks] = (uint32_t)(row * 64 + ((ch ^ ((row >> 1) & 3)) << 4));
            }
#pragma unroll
        for (int ntp = 0; ntp < 2; ntp++)
#pragma unroll
            for (int ks = 0; ks < 2; ks++) {
                int row = warp_n * 32 + ntp * 16 + ((mat >> 1) << 3) + r;
                int ch  = ks * 2 + (mat & 1);
                b_off[ntp][ks] = (uint32_t)(row * 64 + ((ch ^ ((row >> 1) & 3)) << 4));
            }
    }

    float c[4][4][4];
#pragma unroll
    for (int i = 0; i < 4; i++)
#pragma unroll
        for (int j = 0; j < 4; j++)
#pragma unroll
            for (int q = 0; q < 4; q++) c[i][j][q] = 0.f;

    const int NIT = K / TBKH;   // 32

    // prologue: stages 0..2
#pragma unroll
    for (int s = 0; s < 3; s++) {
#pragma unroll
        for (int r = 0; r < 2; r++) {
            cp16(sA[s] + a_rel[r], a_src[r] + s * TBKH);
            cp16(sB[s] + a_rel[r], b_src[r] + s * TBKH);
        }
        CP_COMMIT();
    }

    int buf = 0, nxt = 3;
    for (int it = 0; it < NIT; it++) {
        if (it + 3 < NIT) {
            const int k0 = (it + 3) * TBKH;
#pragma unroll
            for (int r = 0; r < 2; r++) {
                cp16(sA[nxt] + a_rel[r], a_src[r] + k0);
                cp16(sB[nxt] + a_rel[r], b_src[r] + k0);
            }
        }
        CP_COMMIT();
        CP_WAIT(3);
        __syncthreads();

#pragma unroll
        for (int ks = 0; ks < 2; ks++) {
            uint32_t af[4][4];
#pragma unroll
            for (int mt = 0; mt < 4; mt++)
                ldsm_x4(sA[buf] + a_off[mt][ks], af[mt][0], af[mt][1], af[mt][2], af[mt][3]);
            uint32_t bf[2][4];
#pragma unroll
            for (int ntp = 0; ntp < 2; ntp++)
                ldsm_x4(sB[buf] + b_off[ntp][ks], bf[ntp][0], bf[ntp][1], bf[ntp][2], bf[ntp][3]);
#pragma unroll
            for (int mt = 0; mt < 4; mt++)
#pragma unroll
                for (int nt = 0; nt < 4; nt++) {
                    const uint32_t* bp = &bf[nt >> 1][(nt & 1) * 2];
                    mma_f16(c[mt][nt][0], c[mt][nt][1], c[mt][nt][2], c[mt][nt][3],
                            af[mt][0], af[mt][1], af[mt][2], af[mt][3], bp[0], bp[1]);
                }
        }
        __syncthreads();
        buf = (buf + 1) & (GSTG - 1);
        nxt = (nxt + 1) & (GSTG - 1);
    }

    const int rql = lane >> 2;
    const int cpl = (lane & 3) * 2;
#pragma unroll
    for (int mt = 0; mt < 4; mt++) {
        int rg = row0 + warp_m * 64 + mt * 16 + rql;
#pragma unroll
        for (int nt = 0; nt < 4; nt++) {
            int cg = col0 + warp_n * 32 + nt * 8 + cpl;
            if (HALF_OUT) {
                __half* C = (__half*)Cv;
                *(uint32_t*)(C + (size_t)rg * N + cg)       = pack_h2(c[mt][nt][0], c[mt][nt][1]);
                *(uint32_t*)(C + (size_t)(rg + 8) * N + cg) = pack_h2(c[mt][nt][2], c[mt][nt][3]);
            } else {
                float* C = (float*)Cv;
                float2 v0 = {c[mt][nt][0], c[mt][nt][1]};
                float2 v1 = {c[mt][nt][2], c[mt][nt][3]};
                *(float2*)(C + (size_t)rg * N + cg)       = v0;
                *(float2*)(C + (size_t)(rg + 8) * N + cg) = v1;
            }
        }
    }
}

// ---------------------------------------------------------------------------
// fp16 causal flash attention (same structure as R6, 2 CTAs/SM).
// ---------------------------------------------------------------------------
#define ATT_SCALE 0.18033688f
#define ATT_SMEM  49152

__global__ __launch_bounds__(256, 2)
void attn_f16(const __half* __restrict__ qkv, __half* __restrict__ y) {
    extern __shared__ uint32_t smu[];
    char* smc = (char*)smu;
    const uint32_t qs_base = smem_u32(smu);
    const uint32_t ks_base = qs_base + 16384;
    const uint32_t vs_base = ks_base + 16384;

    const int tid  = threadIdx.x;
    const int lane = tid & 31;
    const int w    = tid >> 5;
    const int qi   = (S_LEN / 128 - 1) - blockIdx.x;
    const int h    = blockIdx.y;
    const int b    = blockIdx.z;
    const int q0   = qi * 128;

    const __half* qb = qkv + (size_t)b * S_LEN * D3 + h * DH;
    const __half* kb = qb + D_MODEL;
    const __half* vb = qb + 2 * D_MODEL;

    int l_row[2], l_chk[2];
    uint32_t l_rel[2];
#pragma unroll
    for (int r = 0; r < 2; r++) {
        int idx = tid + 256 * r;
        l_row[r] = idx >> 3; l_chk[r] = idx & 7;
        l_rel[r] = (uint32_t)(l_row[r] * 128 + ((l_chk[r] ^ (l_row[r] & 7)) << 4));
    }

#pragma unroll
    for (int r = 0; r < 2; r++) {
        cp16(ks_base + l_rel[r], kb + (size_t)l_row[r] * D3 + l_chk[r] * 8);
        cp16(vs_base + l_rel[r], vb + (size_t)l_row[r] * D3 + l_chk[r] * 8);
    }
    CP_COMMIT();

#pragma unroll
    for (int r = 0; r < 4; r++) {
        int idx = tid + 256 * r, row = idx >> 3, ch = idx & 7;
        uint4 raw = *(const uint4*)(qb + (size_t)(q0 + row) * D3 + ch * 8);
        uint32_t* rp = (uint32_t*)&raw;
        uint4 outv;
        uint32_t* op = (uint32_t*)&outv;
#pragma unroll
        for (int j = 0; j < 4; j++) {
            __half2 hv = *(__half2*)&rp[j];
            float2 f = __half22float2(hv);
            op[j] = pack_h2(f.x * ATT_SCALE, f.y * ATT_SCALE);
        }
        *(uint4*)(smc + row * 128 + ((ch ^ (row & 7)) << 4)) = outv;
    }
    CP_WAIT(0);
    __syncthreads();

    const int mat = lane >> 3, rr = lane & 7;
    uint32_t qf[4][4];
    {
        int rowA = w * 16 + ((mat & 1) << 3) + rr;
        int rbase = rowA * 128;
        int rx = rowA & 7;
#pragma unroll
        for (int ks = 0; ks < 4; ks++) {
            int ch = ks * 2 + (mat >> 1);
            ldsm_x4(qs_base + rbase + ((ch ^ rx) << 4), qf[ks][0], qf[ks][1], qf[ks][2], qf[ks][3]);
        }
    }
    uint32_t krowOff[4]; int krx[4];
#pragma unroll
    for (int ntp = 0; ntp < 4; ntp++) {
        int rowB = ntp * 16 + ((mat >> 1) << 3) + rr;
        krowOff[ntp] = (uint32_t)(rowB * 128);
        krx[ntp] = rowB & 7;
    }
    const int kbit = mat & 1;
    uint32_t vrowOff[4]; int vrx[4];
#pragma unroll
    for (int kt = 0; kt < 4; kt++) {
        int rowV = kt * 16 + ((mat & 1) << 3) + rr;
        vrowOff[kt] = (uint32_t)(rowV * 128);
        vrx[kt] = rowV & 7;
    }
    const int vbit = mat >> 1;

    float m_lo = -1e30f, m_hi = -1e30f, l_lo = 0.f, l_hi = 0.f;
    float co[8][4];
#pragma unroll
    for (int i = 0; i < 8; i++)
#pragma unroll
        for (int q = 0; q < 4; q++) co[i][q] = 0.f;

    const int rlo  = q0 + w * 16 + (lane >> 2);
    const int jsel = lane & 3;

    const int njb = 2 * qi + 2;
    int buf = 0;

    for (int jb = 0; jb < njb; jb++) {
        if (jb + 1 < njb) {
            const int kn = (jb + 1) * 64;
            const uint32_t kd = ks_base + (buf ^ 1) * 8192;
            const uint32_t vd = vs_base + (buf ^ 1) * 8192;
#pragma unroll
            for (int r = 0; r < 2; r++) {
                cp16(kd + l_rel[r], kb + (size_t)(kn + l_row[r]) * D3 + l_chk[r] * 8);
                cp16(vd + l_rel[r], vb + (size_t)(kn + l_row[r]) * D3 + l_chk[r] * 8);
            }
        }
        CP_COMMIT();

        const uint32_t kbuf = ks_base + (uint32_t)(buf * 8192);
        const uint32_t vbuf = vs_base + (uint32_t)(buf * 8192);

        float cs[8][4];
#pragma unroll
        for (int i = 0; i < 8; i++)
#pragma unroll
            for (int q = 0; q < 4; q++) cs[i][q] = 0.f;

#pragma unroll
        for (int ks = 0; ks < 4; ks++) {
            uint32_t bf[4][4];
            int ch = ks * 2 + kbit;
#pragma unroll
            for (int ntp = 0; ntp < 4; ntp++)
                ldsm_x4(kbuf + krowOff[ntp] + ((ch ^ krx[ntp]) << 4),
                        bf[ntp][0], bf[ntp][1], bf[ntp][2], bf[ntp][3]);
#pragma unroll
            for (int nt = 0; nt < 8; nt++) {
                const uint32_t* bp = &bf[nt >> 1][(nt & 1) * 2];
                mma_f16(cs[nt][0], cs[nt][1], cs[nt][2], cs[nt][3],
                        qf[ks][0], qf[ks][1], qf[ks][2], qf[ks][3], bp[0], bp[1]);
            }
        }

        if (jb * 64 >= q0) {
#pragma unroll
            for (int nt = 0; nt < 8; nt++) {
                int cb = jb * 64 + nt * 8 + 2 * jsel;
                if (cb     > rlo)     cs[nt][0] = -1e30f;
                if (cb + 1 > rlo)     cs[nt][1] = -1e30f;
                if (cb     > rlo + 8) cs[nt][2] = -1e30f;
                if (cb + 1 > rlo + 8) cs[nt][3] = -1e30f;
            }
        }

        float ml = -1e30f, mh = -1e30f;
#pragma unroll
        for (int nt = 0; nt < 8; nt++) {
            ml = fmaxf(ml, fmaxf(cs[nt][0], cs[nt][1]));
            mh = fmaxf(mh, fmaxf(cs[nt][2], cs[nt][3]));
        }
        ml = fmaxf(ml, __shfl_xor_sync(0xffffffffu, ml, 1));
        ml = fmaxf(ml, __shfl_xor_sync(0xffffffffu, ml, 2));
        mh = fmaxf(mh, __shfl_xor_sync(0xffffffffu, mh, 1));
        mh = fmaxf(mh, __shfl_xor_sync(0xffffffffu, mh, 2));
        float Ml = fmaxf(m_lo, ml), Mh = fmaxf(m_hi, mh);
        float al = ex2f(m_lo - Ml), ah = ex2f(m_hi - Mh);
        m_lo = Ml; m_hi = Mh;

        float sl = 0.f, sh2 = 0.f;
#pragma unroll
        for (int nt = 0; nt < 8; nt++) {
            cs[nt][0] = ex2f(cs[nt][0] - Ml);
            cs[nt][1] = ex2f(cs[nt][1] - Ml);
            cs[nt][2] = ex2f(cs[nt][2] - Mh);
            cs[nt][3] = ex2f(cs[nt][3] - Mh);
            sl  += cs[nt][0] + cs[nt][1];
            sh2 += cs[nt][2] + cs[nt][3];
        }
        sl  += __shfl_xor_sync(0xffffffffu, sl, 1);
        sl  += __shfl_xor_sync(0xffffffffu, sl, 2);
        sh2 += __shfl_xor_sync(0xffffffffu, sh2, 1);
        sh2 += __shfl_xor_sync(0xffffffffu, sh2, 2);
        l_lo = l_lo * al + sl;
        l_hi = l_hi * ah + sh2;
#pragma unroll
        for (int i = 0; i < 8; i++) {
            co[i][0] *= al; co[i][1] *= al; co[i][2] *= ah; co[i][3] *= ah;
        }

#pragma unroll
        for (int kt = 0; kt < 4; kt++) {
            uint32_t pa0 = pack_h2(cs[2 * kt][0],     cs[2 * kt][1]);
            uint32_t pa1 = pack_h2(cs[2 * kt][2],     cs[2 * kt][3]);
            uint32_t pa2 = pack_h2(cs[2 * kt + 1][0], cs[2 * kt + 1][1]);
            uint32_t pa3 = pack_h2(cs[2 * kt + 1][2], cs[2 * kt + 1][3]);

#pragma unroll
            for (int ntp = 0; ntp < 4; ntp++) {
                uint32_t bf0, bf1, bf2, bf3;
                int ch = ntp * 2 + vbit;
                ldsm_x4t(vbuf + vrowOff[kt] + ((ch ^ vrx[kt]) << 4), bf0, bf1, bf2, bf3);
                mma_f16(co[2 * ntp][0], co[2 * ntp][1], co[2 * ntp][2], co[2 * ntp][3],
                        pa0, pa1, pa2, pa3, bf0, bf1);
                mma_f16(co[2 * ntp + 1][0], co[2 * ntp + 1][1], co[2 * ntp + 1][2], co[2 * ntp + 1][3],
                        pa0, pa1, pa2, pa3, bf2, bf3);
            }
        }

        CP_WAIT(0);
        __syncthreads();
        buf ^= 1;
    }

    const float il = 1.0f / l_lo, ih = 1.0f / l_hi;
    __half* yb = y + ((size_t)b * S_LEN + q0 + w * 16 + (lane >> 2)) * D_MODEL + h * DH + 2 * jsel;
#pragma unroll
    for (int nt = 0; nt < 8; nt++) {
        *(uint32_t*)(yb + nt * 8)                       = pack_h2(co[nt][0] * il, co[nt][1] * il);
        *(uint32_t*)(yb + nt * 8 + 8 * (size_t)D_MODEL) = pack_h2(co[nt][2] * ih, co[nt][3] * ih);
    }
}

// ---------------------------------------------------------------------------
extern "C" void kernel_launch(void* const* d_in, const int* in_sizes, int n_in,
                              void* d_out, int out_size) {
    const float* x      = (const float*)d_in[0];
    const float* w_attn = (const float*)d_in[1];
    const float* w_proj = (const float*)d_in[2];
    float* out = (float*)d_out;

    __half *qkv, *yb, *xc, *wac, *wpc;
    cudaGetSymbolAddress((void**)&qkv, g_qkv);
    cudaGetSymbolAddress((void**)&yb, g_y);
    cudaGetSymbolAddress((void**)&xc, g_xc);
    cudaGetSymbolAddress((void**)&wac, g_wac);
    cudaGetSymbolAddress((void**)&wpc, g_wpc);

    cudaFuncSetAttribute(gemm_f16<true>,  cudaFuncAttributeMaxDynamicSharedMemorySize, GEMM_SMEM);
    cudaFuncSetAttribute(gemm_f16<false>, cudaFuncAttributeMaxDynamicSharedMemorySize, GEMM_SMEM);
    cudaFuncSetAttribute(attn_f16, cudaFuncAttributeMaxDynamicSharedMemorySize, ATT_SMEM);

    round_f16<<<(M_ROWS * D_MODEL / 4 + 255) / 256, 256>>>(x, xc, M_ROWS * D_MODEL / 4);
    round_f16<<<(D3 * D_MODEL / 4 + 255) / 256, 256>>>(w_attn, wac, D3 * D_MODEL / 4);
    round_f16<<<(D_MODEL * D_MODEL / 4 + 255) / 256, 256>>>(w_proj, wpc, D_MODEL * D_MODEL / 4);

    dim3 g1(D3 / TBN, M_ROWS / TBM);
    gemm_f16<true><<<g1, 256, GEMM_SMEM>>>(xc, wac, qkv, M_ROWS, D3, D_MODEL);

    dim3 ga(S_LEN / 128, N_HEADS, BATCH);
    attn_f16<<<ga, 256, ATT_SMEM>>>(qkv, yb);

    dim3 g2(D_MODEL / TBN, M_ROWS / TBM);
    gemm_f16<false><<<g2, 256, GEMM_SMEM>>>(yb, wpc, out, M_ROWS, D_MODEL, D_MODEL);
}